// round 14
// baseline (speedup 1.0000x reference)
#include <cuda_runtime.h>
#include <cuda_fp16.h>
#include <math.h>
#include <stdint.h>

#define T_TOK   1024
#define DIM     512
#define INTER   256
#define SINTER  1024
#define NEXP    64
#define TOPK    6
#define KC      32
#define KSPLIT  4

// A smem: fp16 planes as u32 (fp16x2); row stride 20 u32 = 80 B (conflict-free)
#define AK2      20
#define APL      (64 * AK2)
#define ABUF_U32 (2 * APL)
#define A_BYTES  (2 * ABUF_U32 * 4)  // 20480 B

// B [n][k] fp32 (expert up): 256 rows, stride 40 floats
#define BF_ST   40
#define BF_FB   (256 * BF_ST)
// B [n][k] fp16 (shared up / final): 256 rows, stride 40 halves
#define BH_ST   40
#define BH_HB   (256 * BH_ST)
// B [k][n] fp32 (down): 32 rows, stride 260 floats
#define BKN_ST  260
#define BKN_FB  (32 * BKN_ST)

// ---------------- scratch (device globals; no allocation) ----------------
__device__ int      g_topk_idx[T_TOK * TOPK];
__device__ float    g_topk_w[T_TOK * TOPK];
__device__ int      g_counts[NEXP];
__device__ int      g_tok[NEXP * T_TOK];
__device__ int      g_tslot[NEXP * T_TOK];
__device__ float    g_tw[NEXP * T_TOK];
__device__ float    g_contrib[T_TOK * TOPK * DIM];
__device__ float    g_part[KSPLIT * T_TOK * DIM];
__device__ uint32_t g_he_hi[NEXP * T_TOK * (INTER / 2)];
__device__ uint32_t g_he_lo[NEXP * T_TOK * (INTER / 2)];
__device__ uint32_t g_hs_hi[T_TOK * (SINTER / 2)];
__device__ uint32_t g_hs_lo[T_TOK * (SINTER / 2)];
// fp16 SHARED-expert weights (6 MB; converted once per launch)
__device__ __align__(16) __half g_wsgh[SINTER * DIM];
__device__ __align__(16) __half g_wsuh[SINTER * DIM];
__device__ __align__(16) __half g_wsdh[DIM * SINTER];

// ---------------- helpers ----------------
__device__ __forceinline__ void splitp(float2 v, uint32_t& hi, uint32_t& lo) {
    __half2 h = __floats2half2_rn(v.x, v.y);
    float2  b = __half22float2(h);
    __half2 l = __floats2half2_rn(v.x - b.x, v.y - b.y);
    hi = *reinterpret_cast<uint32_t*>(&h);
    lo = *reinterpret_cast<uint32_t*>(&l);
}
__device__ __forceinline__ uint32_t h2bits(float a, float b) {
    __half2 h = __floats2half2_rn(a, b);
    return *reinterpret_cast<uint32_t*>(&h);
}
__device__ __forceinline__ void mma16(float c[4], const uint32_t a[4],
                                      uint32_t b0, uint32_t b1) {
    asm volatile(
        "mma.sync.aligned.m16n8k16.row.col.f32.f16.f16.f32 "
        "{%0,%1,%2,%3}, {%4,%5,%6,%7}, {%8,%9}, {%0,%1,%2,%3};"
        : "+f"(c[0]), "+f"(c[1]), "+f"(c[2]), "+f"(c[3])
        : "r"(a[0]), "r"(a[1]), "r"(a[2]), "r"(a[3]), "r"(b0), "r"(b1));
}
__device__ __forceinline__ void cp16(void* dst_smem, const void* src) {
    uint32_t d = (uint32_t)__cvta_generic_to_shared(dst_smem);
    asm volatile("cp.async.cg.shared.global [%0], [%1], 16;" :: "r"(d), "l"(src));
}
__device__ __forceinline__ void cpcommit() {
    asm volatile("cp.async.commit_group;" ::: "memory");
}
template <int N> __device__ __forceinline__ void cpwait() {
    asm volatile("cp.async.wait_group %0;" :: "n"(N) : "memory");
}
__device__ __forceinline__ uint32_t smaddr(const void* p) {
    return (uint32_t)__cvta_generic_to_shared(p);
}
__device__ __forceinline__ void ldsm4(uint32_t& r0, uint32_t& r1, uint32_t& r2,
                                      uint32_t& r3, uint32_t a) {
    asm volatile("ldmatrix.sync.aligned.m8n8.x4.shared.b16 {%0,%1,%2,%3}, [%4];"
                 : "=r"(r0), "=r"(r1), "=r"(r2), "=r"(r3) : "r"(a));
}

// ---------------- 0. shared-weight conversion fp32 -> fp16 ----------------
__global__ __launch_bounds__(256) void conv3_kernel(
    const float* __restrict__ s0, __half* __restrict__ d0,
    const float* __restrict__ s1, __half* __restrict__ d1,
    const float* __restrict__ s2, __half* __restrict__ d2, int n8)
{
    const float* s = (blockIdx.y == 0) ? s0 : (blockIdx.y == 1) ? s1 : s2;
    __half*      d = (blockIdx.y == 0) ? d0 : (blockIdx.y == 1) ? d1 : d2;
    int i = blockIdx.x * 256 + threadIdx.x;
    int stride = gridDim.x * 256;
    for (; i < n8; i += stride) {
        float4 v0 = ((const float4*)s)[2 * i];
        float4 v1 = ((const float4*)s)[2 * i + 1];
        __half2 h0 = __floats2half2_rn(v0.x, v0.y);
        __half2 h1 = __floats2half2_rn(v0.z, v0.w);
        __half2 h2 = __floats2half2_rn(v1.x, v1.y);
        __half2 h3 = __floats2half2_rn(v1.z, v1.w);
        uint4 o;
        o.x = *(uint32_t*)&h0; o.y = *(uint32_t*)&h1;
        o.z = *(uint32_t*)&h2; o.w = *(uint32_t*)&h3;
        ((uint4*)d)[i] = o;
    }
}

// ---------------- 1. router ----------------
__global__ __launch_bounds__(256) void router_kernel(
    const float* __restrict__ x, const float* __restrict__ wg)
{
    const int t0  = blockIdx.x * 16;
    const int tid = threadIdx.x;
    __shared__ float xs[16 * DIM];
    __shared__ float sc[16 * NEXP];

    for (int idx = tid; idx < 16 * DIM / 4; idx += 256)
        *(float4*)&xs[idx * 4] = *(const float4*)&x[(size_t)t0 * DIM + idx * 4];
    __syncthreads();

    int e  = tid & 63;
    int tg = tid >> 6;
    const float4* wr = (const float4*)(wg + (size_t)e * DIM);
    for (int tt = tg; tt < 16; tt += 4) {
        float acc = 0.f;
        #pragma unroll 4
        for (int d4 = 0; d4 < DIM / 4; d4++) {
            float4 w  = wr[d4];
            float4 xv = *(const float4*)&xs[tt * DIM + d4 * 4];
            acc = fmaf(w.x, xv.x, fmaf(w.y, xv.y, fmaf(w.z, xv.z, fmaf(w.w, xv.w, acc))));
        }
        sc[tt * NEXP + e] = acc;
    }
    __syncthreads();

    if (tid < 16) {
        float* s = &sc[tid * NEXP];
        float vals[TOPK]; int idx[TOPK];
        for (int k = 0; k < TOPK; k++) {
            float best = -INFINITY; int bi = 0;
            for (int ee = 0; ee < NEXP; ee++)
                if (s[ee] > best) { best = s[ee]; bi = ee; }
            vals[k] = best; idx[k] = bi; s[bi] = -INFINITY;
        }
        float mx = vals[0];
        float w6[TOPK]; float sum = 0.f;
        #pragma unroll
        for (int k = 0; k < TOPK; k++) { w6[k] = __expf(vals[k] - mx); sum += w6[k]; }
        float inv = 1.f / sum;
        int t = t0 + tid;
        #pragma unroll
        for (int k = 0; k < TOPK; k++) {
            g_topk_idx[t * TOPK + k] = idx[k];
            g_topk_w[t * TOPK + k]   = w6[k] * inv;
        }
    }
}

// ---------------- 2. deterministic grouping (ballot scan) ----------------
__global__ __launch_bounds__(1024) void group_kernel()
{
    int e = blockIdx.x;
    int t = threadIdx.x;
    int warp = t >> 5, lane = t & 31;
    int slot = -1;
    #pragma unroll
    for (int k = 0; k < TOPK; k++)
        if (g_topk_idx[t * TOPK + k] == e) slot = k;
    unsigned mask = __ballot_sync(0xffffffffu, slot >= 0);

    __shared__ int wbase[32];
    if (lane == 0) wbase[warp] = __popc(mask);
    __syncthreads();
    if (t < 32) {
        int v = wbase[t];
        int s = v;
        #pragma unroll
        for (int off = 1; off < 32; off <<= 1) {
            int u = __shfl_up_sync(0xffffffffu, s, off);
            if (t >= off) s += u;
        }
        wbase[t] = s - v;
        if (t == 31) g_counts[e] = s;
    }
    __syncthreads();
    if (slot >= 0) {
        int pos = wbase[warp] + __popc(mask & ((1u << lane) - 1u));
        g_tok[e * T_TOK + pos]   = t;
        g_tslot[e * T_TOK + pos] = slot;
        g_tw[e * T_TOK + pos]    = g_topk_w[t * TOPK + slot];
    }
}

// ---------------- 3. fused gate+up projection (experts + shared) ----------
// grid (16, NEXP*2 + SINTER/128)
__global__ __launch_bounds__(256, 2) void up_mma(const float* __restrict__ x,
    const float* __restrict__ w1, const float* __restrict__ w3)
{
    extern __shared__ __align__(16) char smc[];
    uint32_t* Au  = (uint32_t*)smc;              // [2 buf][2 plane][64][AK2]
    float*    Bf  = (float*)(smc + A_BYTES);     // expert: [2][256][BF_ST] fp32
    __half*   Bh  = (__half*)(smc + A_BYTES);    // shared: [2][256][BH_ST] fp16

    const int by = blockIdx.y;
    const bool is_shared = (by >= NEXP * 2);
    const int tid  = threadIdx.x;
    const int wid  = tid >> 5;
    const int lane = tid & 31;
    const int gid  = lane >> 2;
    const int l4   = lane & 3;
    const int m0   = blockIdx.x * 64;

    __shared__ int s_row[64];

    int e = 0, ncol0 = 0, mr = 64;
    const float  *Wgf = nullptr, *Wuf = nullptr;
    const __half *Wgh = nullptr, *Wuh = nullptr;
    if (is_shared) {
        int js = by - NEXP * 2;
        ncol0 = js * 128;
        Wgh = g_wsgh + (size_t)ncol0 * DIM;
        Wuh = g_wsuh + (size_t)ncol0 * DIM;
        if (tid < 64) s_row[tid] = m0 + tid;
    } else {
        e = by >> 1;
        int cnt = g_counts[e];
        if (m0 >= cnt) return;
        mr = min(64, cnt - m0);
        int j  = by & 1;
        ncol0 = j * 128;
        Wgf = w1 + (size_t)e * INTER * DIM + (size_t)ncol0 * DIM;
        Wuf = w3 + (size_t)e * INTER * DIM + (size_t)ncol0 * DIM;
        if (tid < 64) s_row[tid] = g_tok[e * T_TOK + m0 + ((tid < mr) ? tid : 0)];
    }
    __syncthreads();
    const int rtmax = (mr + 15) >> 4;

    const int ar  = tid >> 2;
    const int acb = (tid & 3) * 4;
    const float* xrow = x + (size_t)s_row[ar] * DIM;

    const uint32_t a_base = smaddr(Au) + (lane & 15) * 80 + (lane >> 4) * 16;
    const uint32_t bh_base = smaddr(Bh) + (((lane >> 4) & 1) * 8 + (lane & 7)) * 80
                                         + ((lane >> 3) & 1) * 16;
    const int nn[4] = { wid * 16 + gid, wid * 16 + 8 + gid,
                        128 + wid * 16 + gid, 128 + wid * 16 + 8 + gid };

    float c[4][4][4];   // ct 0..1 = gate cols, ct 2..3 = up cols
    #pragma unroll
    for (int i = 0; i < 4; i++)
        #pragma unroll
        for (int j = 0; j < 4; j++)
            #pragma unroll
            for (int q = 0; q < 4; q++) c[i][j][q] = 0.f;

    float4 pa0 = *(const float4*)(xrow + acb * 2);
    float4 pa1 = *(const float4*)(xrow + acb * 2 + 4);

    const int NCH = DIM / KC;   // 16

    if (!is_shared) {
        // ---- expert path: B fp32, cvt at fragment build ----
        #pragma unroll
        for (int j = 0; j < 8; j++) {
            int idx = tid + 256 * j;
            int row = idx >> 3, col = (idx & 7) * 4;
            const float* src = (row < 128) ? (Wgf + (size_t)row * DIM + col)
                                           : (Wuf + (size_t)(row - 128) * DIM + col);
            cp16(&Bf[row * BF_ST + col], src);
        }
        cpcommit();
        for (int kc = 0; kc < NCH; kc++) {
            int st = kc & 1;
            {
                uint32_t h0, l0, h1, l1, h2, l2, h3, l3;
                splitp(make_float2(pa0.x, pa0.y), h0, l0);
                splitp(make_float2(pa0.z, pa0.w), h1, l1);
                splitp(make_float2(pa1.x, pa1.y), h2, l2);
                splitp(make_float2(pa1.z, pa1.w), h3, l3);
                uint32_t* d = Au + st * ABUF_U32 + ar * AK2 + acb;
                *(uint4*)d         = make_uint4(h0, h1, h2, h3);
                *(uint4*)(d + APL) = make_uint4(l0, l1, l2, l3);
            }
            cpwait<0>();
            __syncthreads();
            if (kc < NCH - 1) {
                int kb = (kc + 1) * KC;
                int sn = st ^ 1;
                pa0 = *(const float4*)(xrow + kb + acb * 2);
                pa1 = *(const float4*)(xrow + kb + acb * 2 + 4);
                #pragma unroll
                for (int j = 0; j < 8; j++) {
                    int idx = tid + 256 * j;
                    int row = idx >> 3, col = (idx & 7) * 4;
                    const float* src = (row < 128) ? (Wgf + (size_t)row * DIM + kb + col)
                                                   : (Wuf + (size_t)(row - 128) * DIM + kb + col);
                    cp16(&Bf[sn * BF_FB + row * BF_ST + col], src);
                }
                cpcommit();
            }
            uint32_t ab = a_base + st * (ABUF_U32 * 4);
            const float* Bsb = Bf + st * BF_FB;
            if (mr == 64) {
                // full tile: exact R9 schedule
                #pragma unroll
                for (int ks = 0; ks < 2; ks++) {
                    uint32_t bq[8];
                    #pragma unroll
                    for (int ct = 0; ct < 4; ct++) {
                        const float* bp = Bsb + nn[ct] * BF_ST + ks * 16 + 2 * l4;
                        float2 v0 = *(const float2*)bp;
                        float2 v1 = *(const float2*)(bp + 8);
                        bq[2 * ct]     = h2bits(v0.x, v0.y);
                        bq[2 * ct + 1] = h2bits(v1.x, v1.y);
                    }
                    uint32_t ah[4][4];
                    #pragma unroll
                    for (int rt = 0; rt < 4; rt++)
                        ldsm4(ah[rt][0], ah[rt][1], ah[rt][2], ah[rt][3],
                              ab + rt * 1280 + ks * 32);
                    #pragma unroll
                    for (int ct = 0; ct < 4; ct++)
                        #pragma unroll
                        for (int rt = 0; rt < 4; rt++)
                            mma16(c[rt][ct], ah[rt], bq[2 * ct], bq[2 * ct + 1]);
                    uint32_t al[4][4];
                    #pragma unroll
                    for (int rt = 0; rt < 4; rt++)
                        ldsm4(al[rt][0], al[rt][1], al[rt][2], al[rt][3],
                              ab + APL * 4 + rt * 1280 + ks * 32);
                    #pragma unroll
                    for (int ct = 0; ct < 4; ct++)
                        #pragma unroll
                        for (int rt = 0; rt < 4; rt++)
                            mma16(c[rt][ct], al[rt], bq[2 * ct], bq[2 * ct + 1]);
                }
            } else {
                // partial tile: only rt < rtmax
                #pragma unroll
                for (int ks = 0; ks < 2; ks++) {
                    uint32_t bq[8];
                    #pragma unroll
                    for (int ct = 0; ct < 4; ct++) {
                        const float* bp = Bsb + nn[ct] * BF_ST + ks * 16 + 2 * l4;
                        float2 v0 = *(const float2*)bp;
                        float2 v1 = *(const float2*)(bp + 8);
                        bq[2 * ct]     = h2bits(v0.x, v0.y);
                        bq[2 * ct + 1] = h2bits(v1.x, v1.y);
                    }
                    for (int rt = 0; rt < rtmax; rt++) {
                        uint32_t ah[4];
                        ldsm4(ah[0], ah[1], ah[2], ah[3], ab + rt * 1280 + ks * 32);
                        #pragma unroll
                        for (int ct = 0; ct < 4; ct++)
                            mma16(c[rt][ct], ah, bq[2 * ct], bq[2 * ct + 1]);
                        uint32_t al[4];
                        ldsm4(al[0], al[1], al[2], al[3],
                              ab + APL * 4 + rt * 1280 + ks * 32);
                        #pragma unroll
                        for (int ct = 0; ct < 4; ct++)
                            mma16(c[rt][ct], al, bq[2 * ct], bq[2 * ct + 1]);
                    }
                }
            }
        }
    } else {
        // ---- shared path: B fp16, ldmatrix (exact R9) ----
        #pragma unroll
        for (int j = 0; j < 4; j++) {
            int idx = tid + 256 * j;
            int row = idx >> 2, seg = (idx & 3) * 8;
            const __half* src = (row < 128) ? (Wgh + (size_t)row * DIM + seg)
                                            : (Wuh + (size_t)(row - 128) * DIM + seg);
            cp16(Bh + row * BH_ST + seg, src);
        }
        cpcommit();
        for (int kc = 0; kc < NCH; kc++) {
            int st = kc & 1;
            {
                uint32_t h0, l0, h1, l1, h2, l2, h3, l3;
                splitp(make_float2(pa0.x, pa0.y), h0, l0);
                splitp(make_float2(pa0.z, pa0.w), h1, l1);
                splitp(make_float2(pa1.x, pa1.y), h2, l2);
                splitp(make_float2(pa1.z, pa1.w), h3, l3);
                uint32_t* d = Au + st * ABUF_U32 + ar * AK2 + acb;
                *(uint4*)d         = make_uint4(h0, h1, h2, h3);
                *(uint4*)(d + APL) = make_uint4(l0, l1, l2, l3);
            }
            cpwait<0>();
            __syncthreads();
            if (kc < NCH - 1) {
                int kb = (kc + 1) * KC;
                int sn = st ^ 1;
                pa0 = *(const float4*)(xrow + kb + acb * 2);
                pa1 = *(const float4*)(xrow + kb + acb * 2 + 4);
                #pragma unroll
                for (int j = 0; j < 4; j++) {
                    int idx = tid + 256 * j;
                    int row = idx >> 2, seg = (idx & 3) * 8;
                    const __half* src = (row < 128) ? (Wgh + (size_t)row * DIM + kb + seg)
                                                    : (Wuh + (size_t)(row - 128) * DIM + kb + seg);
                    cp16(Bh + sn * BH_HB + row * BH_ST + seg, src);
                }
                cpcommit();
            }
            uint32_t ab = a_base + st * (ABUF_U32 * 4);
            uint32_t bb = bh_base + st * (BH_HB * 2);
            #pragma unroll
            for (int ks = 0; ks < 2; ks++) {
                uint32_t bq[8];
                ldsm4(bq[0], bq[1], bq[2], bq[3], bb + (wid * 16) * 80 + ks * 32);
                ldsm4(bq[4], bq[5], bq[6], bq[7], bb + (128 + wid * 16) * 80 + ks * 32);
                uint32_t ah[4][4];
                #pragma unroll
                for (int rt = 0; rt < 4; rt++)
                    ldsm4(ah[rt][0], ah[rt][1], ah[rt][2], ah[rt][3],
                          ab + rt * 1280 + ks * 32);
                #pragma unroll
                for (int ct = 0; ct < 4; ct++)
                    #pragma unroll
                    for (int rt = 0; rt < 4; rt++)
                        mma16(c[rt][ct], ah[rt], bq[2 * ct], bq[2 * ct + 1]);
                uint32_t al[4][4];
                #pragma unroll
                for (int rt = 0; rt < 4; rt++)
                    ldsm4(al[rt][0], al[rt][1], al[rt][2], al[rt][3],
                          ab + APL * 4 + rt * 1280 + ks * 32);
                #pragma unroll
                for (int ct = 0; ct < 4; ct++)
                    #pragma unroll
                    for (int rt = 0; rt < 4; rt++)
                        mma16(c[rt][ct], al[rt], bq[2 * ct], bq[2 * ct + 1]);
            }
        }
    }

    // epilogue: h = silu(gate)*up -> fp16 planes -> global
    #pragma unroll
    for (int rt = 0; rt < 4; rt++) {
        #pragma unroll
        for (int ct = 0; ct < 2; ct++) {
            int col = ncol0 + wid * 16 + ct * 8 + 2 * l4;
            #pragma unroll
            for (int half = 0; half < 2; half++) {
                int r = rt * 16 + gid + half * 8;
                float g0 = c[rt][ct][half * 2],     u0 = c[rt][ct + 2][half * 2];
                float g1 = c[rt][ct][half * 2 + 1], u1 = c[rt][ct + 2][half * 2 + 1];
                float h0 = (g0 / (1.f + __expf(-g0))) * u0;
                float h1 = (g1 / (1.f + __expf(-g1))) * u1;
                uint32_t hh, hl;
                splitp(make_float2(h0, h1), hh, hl);
                if (is_shared) {
                    size_t gi = (size_t)(m0 + r) * (SINTER / 2) + (col >> 1);
                    g_hs_hi[gi] = hh; g_hs_lo[gi] = hl;
                } else {
                    size_t gi = ((size_t)e * T_TOK + m0 + r) * (INTER / 2) + (col >> 1);
                    g_he_hi[gi] = hh; g_he_lo[gi] = hl;
                }
            }
        }
    }
}

// ---------------- 4. expert down-projection ----------------
// grid (16, NEXP, 2); B fp32 [k][n]; A ldmatrix from fp16 planes
__global__ __launch_bounds__(256, 2) void down_mma(const float* __restrict__ w2)
{
    extern __shared__ __align__(16) char smc[];
    uint32_t* Au = (uint32_t*)smc;               // [2][2 plane][64][AK2]
    float*    Bs = (float*)(smc + A_BYTES);      // [2][32][BKN_ST] fp32 [k][n]

    const int e  = blockIdx.y;
    const int cnt = g_counts[e];
    const int m0 = blockIdx.x * 64;
    if (m0 >= cnt) return;
    const int mr = min(64, cnt - m0);
    const int rtmax = (mr + 15) >> 4;
    const int n0 = blockIdx.z * 256;

    const int tid  = threadIdx.x;
    const int wid  = tid >> 5;
    const int lane = tid & 31;
    const int gid  = lane >> 2;
    const int l4   = lane & 3;

    __shared__ int   s_tok[64];
    __shared__ int   s_slot[64];
    __shared__ float s_w[64];
    if (tid < 64) {
        int mm = (tid < mr) ? tid : 0;
        s_tok[tid]  = g_tok[e * T_TOK + m0 + mm];
        s_slot[tid] = g_tslot[e * T_TOK + m0 + mm];
        s_w[tid]    = g_tw[e * T_TOK + m0 + mm];
    }

    const uint32_t* hhi = g_he_hi + ((size_t)e * T_TOK + m0) * (INTER / 2);
    const uint32_t* hlo = g_he_lo + ((size_t)e * T_TOK + m0) * (INTER / 2);
    const float* w2base = w2 + (size_t)e * INTER * DIM + n0;

    const uint32_t a_base = smaddr(Au) + (lane & 15) * 80 + (lane >> 4) * 16;
    const int nn[4] = { wid * 32 + gid, wid * 32 + 8 + gid,
                        wid * 32 + 16 + gid, wid * 32 + 24 + gid };

    float c[4][4][4];
    #pragma unroll
    for (int i = 0; i < 4; i++)
        #pragma unroll
        for (int j = 0; j < 4; j++)
            #pragma unroll
            for (int q = 0; q < 4; q++) c[i][j][q] = 0.f;

    {
        #pragma unroll
        for (int j = 0; j < 2; j++) {
            int idx = tid + 256 * j;
            int plane = idx >> 8, rem = idx & 255;
            int row = rem >> 2, seg = (rem & 3) * 4;
            const uint32_t* src = (plane ? hlo : hhi) + (size_t)row * (INTER / 2) + seg;
            cp16(Au + plane * APL + row * AK2 + seg, src);
        }
        #pragma unroll
        for (int j = 0; j < 8; j++) {
            int idx = tid + 256 * j;
            int kr = idx >> 6, nc = (idx & 63) * 4;
            cp16(&Bs[kr * BKN_ST + nc], w2base + (size_t)kr * DIM + nc);
        }
        cpcommit();
    }
    const int NCH = INTER / KC;   // 8
    for (int kc = 0; kc < NCH; kc++) {
        int st = kc & 1;
        cpwait<0>();
        __syncthreads();
        if (kc < NCH - 1) {
            int kb2 = (kc + 1) * 16;
            int kb  = (kc + 1) * KC;
            int sn = st ^ 1;
            #pragma unroll
            for (int j = 0; j < 2; j++) {
                int idx = tid + 256 * j;
                int plane = idx >> 8, rem = idx & 255;
                int row = rem >> 2, seg = (rem & 3) * 4;
                const uint32_t* src = (plane ? hlo : hhi) + (size_t)row * (INTER / 2) + kb2 + seg;
                cp16(Au + sn * ABUF_U32 + plane * APL + row * AK2 + seg, src);
            }
            #pragma unroll
            for (int j = 0; j < 8; j++) {
                int idx = tid + 256 * j;
                int kr = idx >> 6, nc = (idx & 63) * 4;
                cp16(&Bs[sn * BKN_FB + kr * BKN_ST + nc],
                     w2base + (size_t)(kb + kr) * DIM + nc);
            }
            cpcommit();
        }
        uint32_t ab = a_base + st * (ABUF_U32 * 4);
        const float* Bsb = Bs + st * BKN_FB;
        if (mr == 64) {
            // full tile: exact R9 schedule
            #pragma unroll
            for (int ks = 0; ks < 2; ks++) {
                uint32_t bq[8];
                #pragma unroll
                for (int ct = 0; ct < 4; ct++) {
                    int n = nn[ct];
                    int kk = ks * 16 + 2 * l4;
                    bq[2 * ct]     = h2bits(Bsb[kk * BKN_ST + n],       Bsb[(kk + 1) * BKN_ST + n]);
                    bq[2 * ct + 1] = h2bits(Bsb[(kk + 8) * BKN_ST + n], Bsb[(kk + 9) * BKN_ST + n]);
                }
                uint32_t ah[4][4];
                #pragma unroll
                for (int rt = 0; rt < 4; rt++)
                    ldsm4(ah[rt][0], ah[rt][1], ah[rt][2], ah[rt][3],
                          ab + rt * 1280 + ks * 32);
                #pragma unroll
                for (int ct = 0; ct < 4; ct++)
                    #pragma unroll
                    for (int rt = 0; rt < 4; rt++)
                        mma16(c[rt][ct], ah[rt], bq[2 * ct], bq[2 * ct + 1]);
                uint32_t al[4][4];
                #pragma unroll
                for (int rt = 0; rt < 4; rt++)
                    ldsm4(al[rt][0], al[rt][1], al[rt][2], al[rt][3],
                          ab + APL * 4 + rt * 1280 + ks * 32);
                #pragma unroll
                for (int ct = 0; ct < 4; ct++)
                    #pragma unroll
                    for (int rt = 0; rt < 4; rt++)
                        mma16(c[rt][ct], al[rt], bq[2 * ct], bq[2 * ct + 1]);
            }
        } else {
            // partial tile
            #pragma unroll
            for (int ks = 0; ks < 2; ks++) {
                uint32_t bq[8];
                #pragma unroll
                for (int ct = 0; ct < 4; ct++) {
                    int n = nn[ct];
                    int kk = ks * 16 + 2 * l4;
                    bq[2 * ct]     = h2bits(Bsb[kk * BKN_ST + n],       Bsb[(kk + 1) * BKN_ST + n]);
                    bq[2 * ct + 1] = h2bits(Bsb[(kk + 8) * BKN_ST + n], Bsb[(kk + 9) * BKN_ST + n]);
                }
                for (int rt = 0; rt < rtmax; rt++) {
                    uint32_t ah[4];
                    ldsm4(ah[0], ah[1], ah[2], ah[3], ab + rt * 1280 + ks * 32);
                    #pragma unroll
                    for (int ct = 0; ct < 4; ct++)
                        mma16(c[rt][ct], ah, bq[2 * ct], bq[2 * ct + 1]);
                    uint32_t al[4];
                    ldsm4(al[0], al[1], al[2], al[3],
                          ab + APL * 4 + rt * 1280 + ks * 32);
                    #pragma unroll
                    for (int ct = 0; ct < 4; ct++)
                        mma16(c[rt][ct], al, bq[2 * ct], bq[2 * ct + 1]);
                }
            }
        }
    }

    #pragma unroll
    for (int rt = 0; rt < 4; rt++) {
        #pragma unroll
        for (int ct = 0; ct < 4; ct++) {
            int col = n0 + wid * 32 + ct * 8 + 2 * l4;
            #pragma unroll
            for (int half = 0; half < 2; half++) {
                int r = rt * 16 + gid + half * 8;
                if (r < mr) {
                    size_t base = ((size_t)(s_tok[r] * TOPK + s_slot[r])) * DIM + col;
                    float w = s_w[r];
                    *(float2*)&g_contrib[base] =
                        make_float2(w * c[rt][ct][half * 2], w * c[rt][ct][half * 2 + 1]);
                }
            }
        }
    }
}

// ---------------- 5. final GEMM split-K(4) (exact R9) ----------------
// grid (16, 2, KSPLIT)
__global__ __launch_bounds__(256, 2) void final_mma()
{
    extern __shared__ __align__(16) char smc[];
    uint32_t* Au = (uint32_t*)smc;               // [2][2 plane][64][AK2]
    __half*   Bs = (__half*)(smc + A_BYTES);     // [2][256][BH_ST]

    const int m0 = blockIdx.x * 64;
    const int n0 = blockIdx.y * 256;
    const int k0 = blockIdx.z * 256;
    const int k02 = k0 / 2;
    const int tid  = threadIdx.x;
    const int wid  = tid >> 5;
    const int lane = tid & 31;
    const int gid  = lane >> 2;
    const int l4   = lane & 3;

    const uint32_t a_base = smaddr(Au) + (lane & 15) * 80 + (lane >> 4) * 16;
    const uint32_t b_base = smaddr(Bs) + (((lane >> 4) & 1) * 8 + (lane & 7)) * 80
                                        + ((lane >> 3) & 1) * 16;

    float c[4][4][4];
    #pragma unroll
    for (int i = 0; i < 4; i++)
        #pragma unroll
        for (int j = 0; j < 4; j++)
            #pragma unroll
            for (int q = 0; q < 4; q++) c[i][j][q] = 0.f;

    {
        #pragma unroll
        for (int j = 0; j < 2; j++) {
            int idx = tid + 256 * j;
            int plane = idx >> 8, rem = idx & 255;
            int row = rem >> 2, seg = (rem & 3) * 4;
            const uint32_t* src = (plane ? g_hs_lo : g_hs_hi)
                                  + (size_t)(m0 + row) * (SINTER / 2) + k02 + seg;
            cp16(Au + plane * APL + row * AK2 + seg, src);
        }
        #pragma unroll
        for (int j = 0; j < 4; j++) {
            int idx = tid + 256 * j;
            int row = idx >> 2, seg = (idx & 3) * 8;
            cp16(Bs + row * BH_ST + seg,
                 g_wsdh + (size_t)(n0 + row) * SINTER + k0 + seg);
        }
        cpcommit();
    }
    const int NCH = 256 / KC;   // 8
    for (int kc = 0; kc < NCH; kc++) {
        int st = kc & 1;
        cpwait<0>();
        __syncthreads();
        if (kc < NCH - 1) {
            int kb  = (kc + 1) * KC;
            int kb2 = (kc + 1) * 16;
            int sn = st ^ 1;
            #pragma unroll
            for (int j = 0; j < 2; j++) {
                int idx = tid + 256 * j;
                int plane = idx >> 8, rem = idx & 255;
                int row = rem >> 2, seg = (rem & 3) * 4;
                const uint32_t* src = (plane ? g_hs_lo : g_hs_hi)
                                      + (size_t)(m0 + row) * (SINTER / 2) + k02 + kb2 + seg;
                cp16(Au + sn * ABUF_U32 + plane * APL + row * AK2 + seg, src);
            }
            #pragma unroll
            for (int j = 0; j < 4; j++) {
                int idx = tid + 256 * j;
                int row = idx >> 2, seg = (idx & 3) * 8;
                cp16(Bs + sn * BH_HB + row * BH_ST + seg,
                     g_wsdh + (size_t)(n0 + row) * SINTER + k0 + kb + seg);
            }
            cpcommit();
        }
        uint32_t ab = a_base + st * (ABUF_U32 * 4);
        uint32_t bb = b_base + st * (BH_HB * 2);
        #pragma unroll
        for (int ks = 0; ks < 2; ks++) {
            uint32_t bq[8];
            ldsm4(bq[0], bq[1], bq[2], bq[3], bb + (wid * 32) * 80 + ks * 32);
            ldsm4(bq[4], bq[5], bq[6], bq[7], bb + (wid * 32 + 16) * 80 + ks * 32);
            uint32_t ah[4][4];
            #pragma unroll
            for (int rt = 0; rt < 4; rt++)
                ldsm4(ah[rt][0], ah[rt][1], ah[rt][2], ah[rt][3],
                      ab + rt * 1280 + ks * 32);
            #pragma unroll
            for (int ct = 0; ct < 4; ct++)
                #pragma unroll
                for (int rt = 0; rt < 4; rt++)
                    mma16(c[rt][ct], ah[rt], bq[2 * ct], bq[2 * ct + 1]);
            uint32_t al[4][4];
            #pragma unroll
            for (int rt = 0; rt < 4; rt++)
                ldsm4(al[rt][0], al[rt][1], al[rt][2], al[rt][3],
                      ab + APL * 4 + rt * 1280 + ks * 32);
            #pragma unroll
            for (int ct = 0; ct < 4; ct++)
                #pragma unroll
                for (int rt = 0; rt < 4; rt++)
                    mma16(c[rt][ct], al[rt], bq[2 * ct], bq[2 * ct + 1]);
        }
    }

    #pragma unroll
    for (int rt = 0; rt < 4; rt++) {
        #pragma unroll
        for (int ct = 0; ct < 4; ct++) {
            int col = n0 + wid * 32 + ct * 8 + 2 * l4;
            int r0 = m0 + rt * 16 + gid, r1 = r0 + 8;
            *(float2*)&g_part[((size_t)blockIdx.z * T_TOK + r0) * DIM + col]
                = make_float2(c[rt][ct][0], c[rt][ct][1]);
            *(float2*)&g_part[((size_t)blockIdx.z * T_TOK + r1) * DIM + col]
                = make_float2(c[rt][ct][2], c[rt][ct][3]);
        }
    }
}

// ---------------- 6. reduce ----------------
__global__ __launch_bounds__(256) void reduce_kernel(float* __restrict__ out)
{
    int t = blockIdx.x;
    #pragma unroll
    for (int h = 0; h < 2; h++) {
        int d = threadIdx.x + h * 256;
        float v = 0.f;
        #pragma unroll
        for (int z = 0; z < KSPLIT; z++)
            v += g_part[((size_t)z * T_TOK + t) * DIM + d];
        #pragma unroll
        for (int k = 0; k < TOPK; k++)
            v += g_contrib[((size_t)t * TOPK + k) * DIM + d];
        out[(size_t)t * DIM + d] = v;
    }
}

// ---------------- launcher ----------------
extern "C" void kernel_launch(void* const* d_in, const int* in_sizes, int n_in,
                              void* d_out, int out_size)
{
    const float* x   = (const float*)d_in[0];
    const float* wg  = (const float*)d_in[1];
    const float* w1  = (const float*)d_in[2];
    const float* w2  = (const float*)d_in[3];
    const float* w3  = (const float*)d_in[4];
    const float* wsg = (const float*)d_in[5];
    const float* wsu = (const float*)d_in[6];
    const float* wsd = (const float*)d_in[7];
    float* out = (float*)d_out;

    __half *wsgh, *wsuh, *wsdh;
    cudaGetSymbolAddress((void**)&wsgh, g_wsgh);
    cudaGetSymbolAddress((void**)&wsuh, g_wsuh);
    cudaGetSymbolAddress((void**)&wsdh, g_wsdh);

    const int smem_up    = A_BYTES + 2 * BF_FB * 4;      // 102400
    const int smem_down  = A_BYTES + 2 * BKN_FB * 4;     // 87040
    const int smem_final = A_BYTES + 2 * BH_HB * 2;      // 61440

    cudaFuncSetAttribute(up_mma,    cudaFuncAttributeMaxDynamicSharedMemorySize, smem_up);
    cudaFuncSetAttribute(down_mma,  cudaFuncAttributeMaxDynamicSharedMemorySize, smem_down);
    cudaFuncSetAttribute(final_mma, cudaFuncAttributeMaxDynamicSharedMemorySize, smem_final);

    conv3_kernel<<<dim3(256, 3), 256>>>(wsg, wsgh, wsu, wsuh, wsd, wsdh,
                                        SINTER * DIM / 8);
    router_kernel<<<T_TOK / 16, 256>>>(x, wg);
    group_kernel<<<NEXP, 1024>>>();
    up_mma<<<dim3(16, NEXP * 2 + SINTER / 128), 256, smem_up>>>(x, w1, w3);
    down_mma<<<dim3(16, NEXP, 2), 256, smem_down>>>(w2);
    final_mma<<<dim3(16, 2, KSPLIT), 256, smem_final>>>();
    reduce_kernel<<<T_TOK, 256>>>(out);
}

// round 15
// speedup vs baseline: 1.5878x; 1.5878x over previous
#include <cuda_runtime.h>
#include <cuda_fp16.h>
#include <math.h>
#include <stdint.h>

#define T_TOK   1024
#define DIM     512
#define INTER   256
#define SINTER  1024
#define NEXP    64
#define TOPK    6
#define KC      32
#define KSPLIT  4

// A smem: fp16 planes as u32 (fp16x2); row stride 20 u32 = 80 B (conflict-free)
#define AK2      20
#define APL      (64 * AK2)
#define ABUF_U32 (2 * APL)
#define A_BYTES  (2 * ABUF_U32 * 4)  // 20480 B

// B [n][k] fp32 (expert up): 256 rows, stride 40 floats
#define BF_ST   40
#define BF_FB   (256 * BF_ST)
// B [n][k] fp16 (shared up / final): 256 rows, stride 40 halves
#define BH_ST   40
#define BH_HB   (256 * BH_ST)
// B [k][n] fp32 (down): 32 rows, stride 260 floats
#define BKN_ST  260
#define BKN_FB  (32 * BKN_ST)

// ---------------- scratch (device globals; no allocation) ----------------
__device__ int      g_topk_idx[T_TOK * TOPK];
__device__ float    g_topk_w[T_TOK * TOPK];
__device__ int      g_counts[NEXP];
__device__ int      g_tok[NEXP * T_TOK];
__device__ int      g_tslot[NEXP * T_TOK];
__device__ float    g_tw[NEXP * T_TOK];
__device__ float    g_contrib[T_TOK * TOPK * DIM];
__device__ float    g_part[KSPLIT * T_TOK * DIM];
__device__ uint32_t g_he_hi[NEXP * T_TOK * (INTER / 2)];
__device__ uint32_t g_he_lo[NEXP * T_TOK * (INTER / 2)];
__device__ uint32_t g_hs_hi[T_TOK * (SINTER / 2)];
__device__ uint32_t g_hs_lo[T_TOK * (SINTER / 2)];
// fp16 SHARED-expert weights only (6 MB; converted once per launch)
__device__ __align__(16) __half g_wsgh[SINTER * DIM];
__device__ __align__(16) __half g_wsuh[SINTER * DIM];
__device__ __align__(16) __half g_wsdh[DIM * SINTER];

// ---------------- helpers ----------------
__device__ __forceinline__ void splitp(float2 v, uint32_t& hi, uint32_t& lo) {
    __half2 h = __floats2half2_rn(v.x, v.y);
    float2  b = __half22float2(h);
    __half2 l = __floats2half2_rn(v.x - b.x, v.y - b.y);
    hi = *reinterpret_cast<uint32_t*>(&h);
    lo = *reinterpret_cast<uint32_t*>(&l);
}
__device__ __forceinline__ uint32_t h2bits(float a, float b) {
    __half2 h = __floats2half2_rn(a, b);
    return *reinterpret_cast<uint32_t*>(&h);
}
__device__ __forceinline__ void mma16(float c[4], const uint32_t a[4],
                                      uint32_t b0, uint32_t b1) {
    asm volatile(
        "mma.sync.aligned.m16n8k16.row.col.f32.f16.f16.f32 "
        "{%0,%1,%2,%3}, {%4,%5,%6,%7}, {%8,%9}, {%0,%1,%2,%3};"
        : "+f"(c[0]), "+f"(c[1]), "+f"(c[2]), "+f"(c[3])
        : "r"(a[0]), "r"(a[1]), "r"(a[2]), "r"(a[3]), "r"(b0), "r"(b1));
}
__device__ __forceinline__ void cp16(void* dst_smem, const void* src) {
    uint32_t d = (uint32_t)__cvta_generic_to_shared(dst_smem);
    asm volatile("cp.async.cg.shared.global [%0], [%1], 16;" :: "r"(d), "l"(src));
}
__device__ __forceinline__ void cpcommit() {
    asm volatile("cp.async.commit_group;" ::: "memory");
}
template <int N> __device__ __forceinline__ void cpwait() {
    asm volatile("cp.async.wait_group %0;" :: "n"(N) : "memory");
}
__device__ __forceinline__ uint32_t smaddr(const void* p) {
    return (uint32_t)__cvta_generic_to_shared(p);
}
__device__ __forceinline__ void ldsm4(uint32_t& r0, uint32_t& r1, uint32_t& r2,
                                      uint32_t& r3, uint32_t a) {
    asm volatile("ldmatrix.sync.aligned.m8n8.x4.shared.b16 {%0,%1,%2,%3}, [%4];"
                 : "=r"(r0), "=r"(r1), "=r"(r2), "=r"(r3) : "r"(a));
}

// ---------------- 0. shared-weight conversion fp32 -> fp16 ----------------
__global__ __launch_bounds__(256) void conv3_kernel(
    const float* __restrict__ s0, __half* __restrict__ d0,
    const float* __restrict__ s1, __half* __restrict__ d1,
    const float* __restrict__ s2, __half* __restrict__ d2, int n8)
{
    const float* s = (blockIdx.y == 0) ? s0 : (blockIdx.y == 1) ? s1 : s2;
    __half*      d = (blockIdx.y == 0) ? d0 : (blockIdx.y == 1) ? d1 : d2;
    int i = blockIdx.x * 256 + threadIdx.x;
    int stride = gridDim.x * 256;
    for (; i < n8; i += stride) {
        float4 v0 = ((const float4*)s)[2 * i];
        float4 v1 = ((const float4*)s)[2 * i + 1];
        __half2 h0 = __floats2half2_rn(v0.x, v0.y);
        __half2 h1 = __floats2half2_rn(v0.z, v0.w);
        __half2 h2 = __floats2half2_rn(v1.x, v1.y);
        __half2 h3 = __floats2half2_rn(v1.z, v1.w);
        uint4 o;
        o.x = *(uint32_t*)&h0; o.y = *(uint32_t*)&h1;
        o.z = *(uint32_t*)&h2; o.w = *(uint32_t*)&h3;
        ((uint4*)d)[i] = o;
    }
}

// ---------------- 1. router ----------------
__global__ __launch_bounds__(256) void router_kernel(
    const float* __restrict__ x, const float* __restrict__ wg)
{
    const int t0  = blockIdx.x * 16;
    const int tid = threadIdx.x;
    __shared__ float xs[16 * DIM];
    __shared__ float sc[16 * NEXP];

    for (int idx = tid; idx < 16 * DIM / 4; idx += 256)
        *(float4*)&xs[idx * 4] = *(const float4*)&x[(size_t)t0 * DIM + idx * 4];
    __syncthreads();

    int e  = tid & 63;
    int tg = tid >> 6;
    const float4* wr = (const float4*)(wg + (size_t)e * DIM);
    for (int tt = tg; tt < 16; tt += 4) {
        float acc = 0.f;
        #pragma unroll 4
        for (int d4 = 0; d4 < DIM / 4; d4++) {
            float4 w  = wr[d4];
            float4 xv = *(const float4*)&xs[tt * DIM + d4 * 4];
            acc = fmaf(w.x, xv.x, fmaf(w.y, xv.y, fmaf(w.z, xv.z, fmaf(w.w, xv.w, acc))));
        }
        sc[tt * NEXP + e] = acc;
    }
    __syncthreads();

    if (tid < 16) {
        float* s = &sc[tid * NEXP];
        float vals[TOPK]; int idx[TOPK];
        for (int k = 0; k < TOPK; k++) {
            float best = -INFINITY; int bi = 0;
            for (int ee = 0; ee < NEXP; ee++)
                if (s[ee] > best) { best = s[ee]; bi = ee; }
            vals[k] = best; idx[k] = bi; s[bi] = -INFINITY;
        }
        float mx = vals[0];
        float w6[TOPK]; float sum = 0.f;
        #pragma unroll
        for (int k = 0; k < TOPK; k++) { w6[k] = __expf(vals[k] - mx); sum += w6[k]; }
        float inv = 1.f / sum;
        int t = t0 + tid;
        #pragma unroll
        for (int k = 0; k < TOPK; k++) {
            g_topk_idx[t * TOPK + k] = idx[k];
            g_topk_w[t * TOPK + k]   = w6[k] * inv;
        }
    }
}

// ---------------- 2. deterministic grouping (ballot scan) ----------------
__global__ __launch_bounds__(1024) void group_kernel()
{
    int e = blockIdx.x;
    int t = threadIdx.x;
    int warp = t >> 5, lane = t & 31;
    int slot = -1;
    #pragma unroll
    for (int k = 0; k < TOPK; k++)
        if (g_topk_idx[t * TOPK + k] == e) slot = k;
    unsigned mask = __ballot_sync(0xffffffffu, slot >= 0);

    __shared__ int wbase[32];
    if (lane == 0) wbase[warp] = __popc(mask);
    __syncthreads();
    if (t < 32) {
        int v = wbase[t];
        int s = v;
        #pragma unroll
        for (int off = 1; off < 32; off <<= 1) {
            int u = __shfl_up_sync(0xffffffffu, s, off);
            if (t >= off) s += u;
        }
        wbase[t] = s - v;
        if (t == 31) g_counts[e] = s;
    }
    __syncthreads();
    if (slot >= 0) {
        int pos = wbase[warp] + __popc(mask & ((1u << lane) - 1u));
        g_tok[e * T_TOK + pos]   = t;
        g_tslot[e * T_TOK + pos] = slot;
        g_tw[e * T_TOK + pos]    = g_topk_w[t * TOPK + slot];
    }
}

// ---------------- 3. fused gate+up projection (experts + shared) ----------
// grid (16, NEXP*2 + SINTER/128)
__global__ __launch_bounds__(256, 2) void up_mma(const float* __restrict__ x,
    const float* __restrict__ w1, const float* __restrict__ w3)
{
    extern __shared__ __align__(16) char smc[];
    uint32_t* Au  = (uint32_t*)smc;              // [2 buf][2 plane][64][AK2]
    float*    Bf  = (float*)(smc + A_BYTES);     // expert: [2][256][BF_ST] fp32
    __half*   Bh  = (__half*)(smc + A_BYTES);    // shared: [2][256][BH_ST] fp16

    const int by = blockIdx.y;
    const bool is_shared = (by >= NEXP * 2);
    const int tid  = threadIdx.x;
    const int wid  = tid >> 5;
    const int lane = tid & 31;
    const int gid  = lane >> 2;
    const int l4   = lane & 3;
    const int m0   = blockIdx.x * 64;

    __shared__ int s_row[64];

    int e = 0, ncol0 = 0;
    const float  *Wgf = nullptr, *Wuf = nullptr;
    const __half *Wgh = nullptr, *Wuh = nullptr;
    if (is_shared) {
        int js = by - NEXP * 2;
        ncol0 = js * 128;
        Wgh = g_wsgh + (size_t)ncol0 * DIM;
        Wuh = g_wsuh + (size_t)ncol0 * DIM;
        if (tid < 64) s_row[tid] = m0 + tid;
    } else {
        e = by >> 1;
        int cnt = g_counts[e];
        if (m0 >= cnt) return;
        int mr = min(64, cnt - m0);
        int j  = by & 1;
        ncol0 = j * 128;
        Wgf = w1 + (size_t)e * INTER * DIM + (size_t)ncol0 * DIM;
        Wuf = w3 + (size_t)e * INTER * DIM + (size_t)ncol0 * DIM;
        if (tid < 64) s_row[tid] = g_tok[e * T_TOK + m0 + ((tid < mr) ? tid : 0)];
    }
    __syncthreads();

    const int ar  = tid >> 2;
    const int acb = (tid & 3) * 4;
    const float* xrow = x + (size_t)s_row[ar] * DIM;

    const uint32_t a_base = smaddr(Au) + (lane & 15) * 80 + (lane >> 4) * 16;
    const uint32_t bh_base = smaddr(Bh) + (((lane >> 4) & 1) * 8 + (lane & 7)) * 80
                                         + ((lane >> 3) & 1) * 16;
    const int nn[4] = { wid * 16 + gid, wid * 16 + 8 + gid,
                        128 + wid * 16 + gid, 128 + wid * 16 + 8 + gid };

    float c[4][4][4];   // ct 0..1 = gate cols, ct 2..3 = up cols
    #pragma unroll
    for (int i = 0; i < 4; i++)
        #pragma unroll
        for (int j = 0; j < 4; j++)
            #pragma unroll
            for (int q = 0; q < 4; q++) c[i][j][q] = 0.f;

    float4 pa0 = *(const float4*)(xrow + acb * 2);
    float4 pa1 = *(const float4*)(xrow + acb * 2 + 4);

    const int NCH = DIM / KC;   // 16

    if (!is_shared) {
        // ---- expert path: B fp32, cvt at fragment build ----
        #pragma unroll
        for (int j = 0; j < 8; j++) {
            int idx = tid + 256 * j;
            int row = idx >> 3, col = (idx & 7) * 4;
            const float* src = (row < 128) ? (Wgf + (size_t)row * DIM + col)
                                           : (Wuf + (size_t)(row - 128) * DIM + col);
            cp16(&Bf[row * BF_ST + col], src);
        }
        cpcommit();
        for (int kc = 0; kc < NCH; kc++) {
            int st = kc & 1;
            {
                uint32_t h0, l0, h1, l1, h2, l2, h3, l3;
                splitp(make_float2(pa0.x, pa0.y), h0, l0);
                splitp(make_float2(pa0.z, pa0.w), h1, l1);
                splitp(make_float2(pa1.x, pa1.y), h2, l2);
                splitp(make_float2(pa1.z, pa1.w), h3, l3);
                uint32_t* d = Au + st * ABUF_U32 + ar * AK2 + acb;
                *(uint4*)d         = make_uint4(h0, h1, h2, h3);
                *(uint4*)(d + APL) = make_uint4(l0, l1, l2, l3);
            }
            cpwait<0>();
            __syncthreads();
            if (kc < NCH - 1) {
                int kb = (kc + 1) * KC;
                int sn = st ^ 1;
                pa0 = *(const float4*)(xrow + kb + acb * 2);
                pa1 = *(const float4*)(xrow + kb + acb * 2 + 4);
                #pragma unroll
                for (int j = 0; j < 8; j++) {
                    int idx = tid + 256 * j;
                    int row = idx >> 3, col = (idx & 7) * 4;
                    const float* src = (row < 128) ? (Wgf + (size_t)row * DIM + kb + col)
                                                   : (Wuf + (size_t)(row - 128) * DIM + kb + col);
                    cp16(&Bf[sn * BF_FB + row * BF_ST + col], src);
                }
                cpcommit();
            }
            uint32_t ab = a_base + st * (ABUF_U32 * 4);
            const float* Bsb = Bf + st * BF_FB;
            #pragma unroll
            for (int ks = 0; ks < 2; ks++) {
                uint32_t bq[8];
                #pragma unroll
                for (int ct = 0; ct < 4; ct++) {
                    const float* bp = Bsb + nn[ct] * BF_ST + ks * 16 + 2 * l4;
                    float2 v0 = *(const float2*)bp;
                    float2 v1 = *(const float2*)(bp + 8);
                    bq[2 * ct]     = h2bits(v0.x, v0.y);
                    bq[2 * ct + 1] = h2bits(v1.x, v1.y);
                }
                uint32_t ah[4][4];
                #pragma unroll
                for (int rt = 0; rt < 4; rt++)
                    ldsm4(ah[rt][0], ah[rt][1], ah[rt][2], ah[rt][3],
                          ab + rt * 1280 + ks * 32);
                #pragma unroll
                for (int ct = 0; ct < 4; ct++)
                    #pragma unroll
                    for (int rt = 0; rt < 4; rt++)
                        mma16(c[rt][ct], ah[rt], bq[2 * ct], bq[2 * ct + 1]);
                uint32_t al[4][4];
                #pragma unroll
                for (int rt = 0; rt < 4; rt++)
                    ldsm4(al[rt][0], al[rt][1], al[rt][2], al[rt][3],
                          ab + APL * 4 + rt * 1280 + ks * 32);
                #pragma unroll
                for (int ct = 0; ct < 4; ct++)
                    #pragma unroll
                    for (int rt = 0; rt < 4; rt++)
                        mma16(c[rt][ct], al[rt], bq[2 * ct], bq[2 * ct + 1]);
            }
        }
    } else {
        // ---- shared path: B fp16, ldmatrix ----
        #pragma unroll
        for (int j = 0; j < 4; j++) {
            int idx = tid + 256 * j;
            int row = idx >> 2, seg = (idx & 3) * 8;
            const __half* src = (row < 128) ? (Wgh + (size_t)row * DIM + seg)
                                            : (Wuh + (size_t)(row - 128) * DIM + seg);
            cp16(Bh + row * BH_ST + seg, src);
        }
        cpcommit();
        for (int kc = 0; kc < NCH; kc++) {
            int st = kc & 1;
            {
                uint32_t h0, l0, h1, l1, h2, l2, h3, l3;
                splitp(make_float2(pa0.x, pa0.y), h0, l0);
                splitp(make_float2(pa0.z, pa0.w), h1, l1);
                splitp(make_float2(pa1.x, pa1.y), h2, l2);
                splitp(make_float2(pa1.z, pa1.w), h3, l3);
                uint32_t* d = Au + st * ABUF_U32 + ar * AK2 + acb;
                *(uint4*)d         = make_uint4(h0, h1, h2, h3);
                *(uint4*)(d + APL) = make_uint4(l0, l1, l2, l3);
            }
            cpwait<0>();
            __syncthreads();
            if (kc < NCH - 1) {
                int kb = (kc + 1) * KC;
                int sn = st ^ 1;
                pa0 = *(const float4*)(xrow + kb + acb * 2);
                pa1 = *(const float4*)(xrow + kb + acb * 2 + 4);
                #pragma unroll
                for (int j = 0; j < 4; j++) {
                    int idx = tid + 256 * j;
                    int row = idx >> 2, seg = (idx & 3) * 8;
                    const __half* src = (row < 128) ? (Wgh + (size_t)row * DIM + kb + seg)
                                                    : (Wuh + (size_t)(row - 128) * DIM + kb + seg);
                    cp16(Bh + sn * BH_HB + row * BH_ST + seg, src);
                }
                cpcommit();
            }
            uint32_t ab = a_base + st * (ABUF_U32 * 4);
            uint32_t bb = bh_base + st * (BH_HB * 2);
            #pragma unroll
            for (int ks = 0; ks < 2; ks++) {
                uint32_t bq[8];
                ldsm4(bq[0], bq[1], bq[2], bq[3], bb + (wid * 16) * 80 + ks * 32);
                ldsm4(bq[4], bq[5], bq[6], bq[7], bb + (128 + wid * 16) * 80 + ks * 32);
                uint32_t ah[4][4];
                #pragma unroll
                for (int rt = 0; rt < 4; rt++)
                    ldsm4(ah[rt][0], ah[rt][1], ah[rt][2], ah[rt][3],
                          ab + rt * 1280 + ks * 32);
                #pragma unroll
                for (int ct = 0; ct < 4; ct++)
                    #pragma unroll
                    for (int rt = 0; rt < 4; rt++)
                        mma16(c[rt][ct], ah[rt], bq[2 * ct], bq[2 * ct + 1]);
                uint32_t al[4][4];
                #pragma unroll
                for (int rt = 0; rt < 4; rt++)
                    ldsm4(al[rt][0], al[rt][1], al[rt][2], al[rt][3],
                          ab + APL * 4 + rt * 1280 + ks * 32);
                #pragma unroll
                for (int ct = 0; ct < 4; ct++)
                    #pragma unroll
                    for (int rt = 0; rt < 4; rt++)
                        mma16(c[rt][ct], al[rt], bq[2 * ct], bq[2 * ct + 1]);
            }
        }
    }

    // epilogue: h = silu(gate)*up in regs -> fp16 planes -> global
    #pragma unroll
    for (int rt = 0; rt < 4; rt++) {
        #pragma unroll
        for (int ct = 0; ct < 2; ct++) {
            int col = ncol0 + wid * 16 + ct * 8 + 2 * l4;
            #pragma unroll
            for (int half = 0; half < 2; half++) {
                int r = rt * 16 + gid + half * 8;
                float g0 = c[rt][ct][half * 2],     u0 = c[rt][ct + 2][half * 2];
                float g1 = c[rt][ct][half * 2 + 1], u1 = c[rt][ct + 2][half * 2 + 1];
                float h0 = (g0 / (1.f + __expf(-g0))) * u0;
                float h1 = (g1 / (1.f + __expf(-g1))) * u1;
                uint32_t hh, hl;
                splitp(make_float2(h0, h1), hh, hl);
                if (is_shared) {
                    size_t gi = (size_t)(m0 + r) * (SINTER / 2) + (col >> 1);
                    g_hs_hi[gi] = hh; g_hs_lo[gi] = hl;
                } else {
                    size_t gi = ((size_t)e * T_TOK + m0 + r) * (INTER / 2) + (col >> 1);
                    g_he_hi[gi] = hh; g_he_lo[gi] = hl;
                }
            }
        }
    }
}

// ---------------- 4. expert down-projection ----------------
// grid (16, NEXP, 2); B fp32 [k][n], cvt at fragment build; A ldmatrix
__global__ __launch_bounds__(256, 2) void down_mma(const float* __restrict__ w2)
{
    extern __shared__ __align__(16) char smc[];
    uint32_t* Au = (uint32_t*)smc;               // [2][2 plane][64][AK2]
    float*    Bs = (float*)(smc + A_BYTES);      // [2][32][BKN_ST] fp32 [k][n]

    const int e  = blockIdx.y;
    const int cnt = g_counts[e];
    const int m0 = blockIdx.x * 64;
    if (m0 >= cnt) return;
    const int mr = min(64, cnt - m0);
    const int n0 = blockIdx.z * 256;

    const int tid  = threadIdx.x;
    const int wid  = tid >> 5;
    const int lane = tid & 31;
    const int gid  = lane >> 2;
    const int l4   = lane & 3;

    __shared__ int   s_tok[64];
    __shared__ int   s_slot[64];
    __shared__ float s_w[64];
    if (tid < 64) {
        int mm = (tid < mr) ? tid : 0;
        s_tok[tid]  = g_tok[e * T_TOK + m0 + mm];
        s_slot[tid] = g_tslot[e * T_TOK + m0 + mm];
        s_w[tid]    = g_tw[e * T_TOK + m0 + mm];
    }

    const uint32_t* hhi = g_he_hi + ((size_t)e * T_TOK + m0) * (INTER / 2);
    const uint32_t* hlo = g_he_lo + ((size_t)e * T_TOK + m0) * (INTER / 2);
    const float* w2base = w2 + (size_t)e * INTER * DIM + n0;

    const uint32_t a_base = smaddr(Au) + (lane & 15) * 80 + (lane >> 4) * 16;
    const int nn[4] = { wid * 32 + gid, wid * 32 + 8 + gid,
                        wid * 32 + 16 + gid, wid * 32 + 24 + gid };

    float c[4][4][4];
    #pragma unroll
    for (int i = 0; i < 4; i++)
        #pragma unroll
        for (int j = 0; j < 4; j++)
            #pragma unroll
            for (int q = 0; q < 4; q++) c[i][j][q] = 0.f;

    {
        #pragma unroll
        for (int j = 0; j < 2; j++) {
            int idx = tid + 256 * j;
            int plane = idx >> 8, rem = idx & 255;
            int row = rem >> 2, seg = (rem & 3) * 4;
            const uint32_t* src = (plane ? hlo : hhi) + (size_t)row * (INTER / 2) + seg;
            cp16(Au + plane * APL + row * AK2 + seg, src);
        }
        #pragma unroll
        for (int j = 0; j < 8; j++) {
            int idx = tid + 256 * j;
            int kr = idx >> 6, nc = (idx & 63) * 4;
            cp16(&Bs[kr * BKN_ST + nc], w2base + (size_t)kr * DIM + nc);
        }
        cpcommit();
    }
    const int NCH = INTER / KC;   // 8
    for (int kc = 0; kc < NCH; kc++) {
        int st = kc & 1;
        cpwait<0>();
        __syncthreads();
        if (kc < NCH - 1) {
            int kb2 = (kc + 1) * 16;
            int kb  = (kc + 1) * KC;
            int sn = st ^ 1;
            #pragma unroll
            for (int j = 0; j < 2; j++) {
                int idx = tid + 256 * j;
                int plane = idx >> 8, rem = idx & 255;
                int row = rem >> 2, seg = (rem & 3) * 4;
                const uint32_t* src = (plane ? hlo : hhi) + (size_t)row * (INTER / 2) + kb2 + seg;
                cp16(Au + sn * ABUF_U32 + plane * APL + row * AK2 + seg, src);
            }
            #pragma unroll
            for (int j = 0; j < 8; j++) {
                int idx = tid + 256 * j;
                int kr = idx >> 6, nc = (idx & 63) * 4;
                cp16(&Bs[sn * BKN_FB + kr * BKN_ST + nc],
                     w2base + (size_t)(kb + kr) * DIM + nc);
            }
            cpcommit();
        }
        uint32_t ab = a_base + st * (ABUF_U32 * 4);
        const float* Bsb = Bs + st * BKN_FB;
        #pragma unroll
        for (int ks = 0; ks < 2; ks++) {
            uint32_t bq[8];
            #pragma unroll
            for (int ct = 0; ct < 4; ct++) {
                int n = nn[ct];
                int kk = ks * 16 + 2 * l4;
                bq[2 * ct]     = h2bits(Bsb[kk * BKN_ST + n],       Bsb[(kk + 1) * BKN_ST + n]);
                bq[2 * ct + 1] = h2bits(Bsb[(kk + 8) * BKN_ST + n], Bsb[(kk + 9) * BKN_ST + n]);
            }
            uint32_t ah[4][4];
            #pragma unroll
            for (int rt = 0; rt < 4; rt++)
                ldsm4(ah[rt][0], ah[rt][1], ah[rt][2], ah[rt][3],
                      ab + rt * 1280 + ks * 32);
            #pragma unroll
            for (int ct = 0; ct < 4; ct++)
                #pragma unroll
                for (int rt = 0; rt < 4; rt++)
                    mma16(c[rt][ct], ah[rt], bq[2 * ct], bq[2 * ct + 1]);
            uint32_t al[4][4];
            #pragma unroll
            for (int rt = 0; rt < 4; rt++)
                ldsm4(al[rt][0], al[rt][1], al[rt][2], al[rt][3],
                      ab + APL * 4 + rt * 1280 + ks * 32);
            #pragma unroll
            for (int ct = 0; ct < 4; ct++)
                #pragma unroll
                for (int rt = 0; rt < 4; rt++)
                    mma16(c[rt][ct], al[rt], bq[2 * ct], bq[2 * ct + 1]);
        }
    }

    #pragma unroll
    for (int rt = 0; rt < 4; rt++) {
        #pragma unroll
        for (int ct = 0; ct < 4; ct++) {
            int col = n0 + wid * 32 + ct * 8 + 2 * l4;
            #pragma unroll
            for (int half = 0; half < 2; half++) {
                int r = rt * 16 + gid + half * 8;
                if (r < mr) {
                    size_t base = ((size_t)(s_tok[r] * TOPK + s_slot[r])) * DIM + col;
                    float w = s_w[r];
                    *(float2*)&g_contrib[base] =
                        make_float2(w * c[rt][ct][half * 2], w * c[rt][ct][half * 2 + 1]);
                }
            }
        }
    }
}

// ---------------- 5. final GEMM split-K(4): part = H @ Wsd^T (fp16 B) ------
// grid (16, 2, KSPLIT)
__global__ __launch_bounds__(256, 2) void final_mma()
{
    extern __shared__ __align__(16) char smc[];
    uint32_t* Au = (uint32_t*)smc;               // [2][2 plane][64][AK2]
    __half*   Bs = (__half*)(smc + A_BYTES);     // [2][256][BH_ST]

    const int m0 = blockIdx.x * 64;
    const int n0 = blockIdx.y * 256;
    const int k0 = blockIdx.z * 256;
    const int k02 = k0 / 2;
    const int tid  = threadIdx.x;
    const int wid  = tid >> 5;
    const int lane = tid & 31;
    const int gid  = lane >> 2;
    const int l4   = lane & 3;

    const uint32_t a_base = smaddr(Au) + (lane & 15) * 80 + (lane >> 4) * 16;
    const uint32_t b_base = smaddr(Bs) + (((lane >> 4) & 1) * 8 + (lane & 7)) * 80
                                        + ((lane >> 3) & 1) * 16;

    float c[4][4][4];
    #pragma unroll
    for (int i = 0; i < 4; i++)
        #pragma unroll
        for (int j = 0; j < 4; j++)
            #pragma unroll
            for (int q = 0; q < 4; q++) c[i][j][q] = 0.f;

    {
        #pragma unroll
        for (int j = 0; j < 2; j++) {
            int idx = tid + 256 * j;
            int plane = idx >> 8, rem = idx & 255;
            int row = rem >> 2, seg = (rem & 3) * 4;
            const uint32_t* src = (plane ? g_hs_lo : g_hs_hi)
                                  + (size_t)(m0 + row) * (SINTER / 2) + k02 + seg;
            cp16(Au + plane * APL + row * AK2 + seg, src);
        }
        #pragma unroll
        for (int j = 0; j < 4; j++) {
            int idx = tid + 256 * j;
            int row = idx >> 2, seg = (idx & 3) * 8;
            cp16(Bs + row * BH_ST + seg,
                 g_wsdh + (size_t)(n0 + row) * SINTER + k0 + seg);
        }
        cpcommit();
    }
    const int NCH = 256 / KC;   // 8
    for (int kc = 0; kc < NCH; kc++) {
        int st = kc & 1;
        cpwait<0>();
        __syncthreads();
        if (kc < NCH - 1) {
            int kb  = (kc + 1) * KC;
            int kb2 = (kc + 1) * 16;
            int sn = st ^ 1;
            #pragma unroll
            for (int j = 0; j < 2; j++) {
                int idx = tid + 256 * j;
                int plane = idx >> 8, rem = idx & 255;
                int row = rem >> 2, seg = (rem & 3) * 4;
                const uint32_t* src = (plane ? g_hs_lo : g_hs_hi)
                                      + (size_t)(m0 + row) * (SINTER / 2) + k02 + kb2 + seg;
                cp16(Au + sn * ABUF_U32 + plane * APL + row * AK2 + seg, src);
            }
            #pragma unroll
            for (int j = 0; j < 4; j++) {
                int idx = tid + 256 * j;
                int row = idx >> 2, seg = (idx & 3) * 8;
                cp16(Bs + sn * BH_HB + row * BH_ST + seg,
                     g_wsdh + (size_t)(n0 + row) * SINTER + k0 + kb + seg);
            }
            cpcommit();
        }
        uint32_t ab = a_base + st * (ABUF_U32 * 4);
        uint32_t bb = b_base + st * (BH_HB * 2);
        #pragma unroll
        for (int ks = 0; ks < 2; ks++) {
            uint32_t bq[8];
            ldsm4(bq[0], bq[1], bq[2], bq[3], bb + (wid * 32) * 80 + ks * 32);
            ldsm4(bq[4], bq[5], bq[6], bq[7], bb + (wid * 32 + 16) * 80 + ks * 32);
            uint32_t ah[4][4];
            #pragma unroll
            for (int rt = 0; rt < 4; rt++)
                ldsm4(ah[rt][0], ah[rt][1], ah[rt][2], ah[rt][3],
                      ab + rt * 1280 + ks * 32);
            #pragma unroll
            for (int ct = 0; ct < 4; ct++)
                #pragma unroll
                for (int rt = 0; rt < 4; rt++)
                    mma16(c[rt][ct], ah[rt], bq[2 * ct], bq[2 * ct + 1]);
            uint32_t al[4][4];
            #pragma unroll
            for (int rt = 0; rt < 4; rt++)
                ldsm4(al[rt][0], al[rt][1], al[rt][2], al[rt][3],
                      ab + APL * 4 + rt * 1280 + ks * 32);
            #pragma unroll
            for (int ct = 0; ct < 4; ct++)
                #pragma unroll
                for (int rt = 0; rt < 4; rt++)
                    mma16(c[rt][ct], al[rt], bq[2 * ct], bq[2 * ct + 1]);
        }
    }

    #pragma unroll
    for (int rt = 0; rt < 4; rt++) {
        #pragma unroll
        for (int ct = 0; ct < 4; ct++) {
            int col = n0 + wid * 32 + ct * 8 + 2 * l4;
            int r0 = m0 + rt * 16 + gid, r1 = r0 + 8;
            *(float2*)&g_part[((size_t)blockIdx.z * T_TOK + r0) * DIM + col]
                = make_float2(c[rt][ct][0], c[rt][ct][1]);
            *(float2*)&g_part[((size_t)blockIdx.z * T_TOK + r1) * DIM + col]
                = make_float2(c[rt][ct][2], c[rt][ct][3]);
        }
    }
}

// ---------------- 6. reduce ----------------
__global__ __launch_bounds__(256) void reduce_kernel(float* __restrict__ out)
{
    int t = blockIdx.x;
    #pragma unroll
    for (int h = 0; h < 2; h++) {
        int d = threadIdx.x + h * 256;
        float v = 0.f;
        #pragma unroll
        for (int z = 0; z < KSPLIT; z++)
            v += g_part[((size_t)z * T_TOK + t) * DIM + d];
        #pragma unroll
        for (int k = 0; k < TOPK; k++)
            v += g_contrib[((size_t)t * TOPK + k) * DIM + d];
        out[(size_t)t * DIM + d] = v;
    }
}

// ---------------- launcher ----------------
extern "C" void kernel_launch(void* const* d_in, const int* in_sizes, int n_in,
                              void* d_out, int out_size)
{
    const float* x   = (const float*)d_in[0];
    const float* wg  = (const float*)d_in[1];
    const float* w1  = (const float*)d_in[2];
    const float* w2  = (const float*)d_in[3];
    const float* w3  = (const float*)d_in[4];
    const float* wsg = (const float*)d_in[5];
    const float* wsu = (const float*)d_in[6];
    const float* wsd = (const float*)d_in[7];
    float* out = (float*)d_out;

    __half *wsgh, *wsuh, *wsdh;
    cudaGetSymbolAddress((void**)&wsgh, g_wsgh);
    cudaGetSymbolAddress((void**)&wsuh, g_wsuh);
    cudaGetSymbolAddress((void**)&wsdh, g_wsdh);

    const int smem_up    = A_BYTES + 2 * BF_FB * 4;      // 102400
    const int smem_down  = A_BYTES + 2 * BKN_FB * 4;     // 87040
    const int smem_final = A_BYTES + 2 * BH_HB * 2;      // 61440

    cudaFuncSetAttribute(up_mma,    cudaFuncAttributeMaxDynamicSharedMemorySize, smem_up);
    cudaFuncSetAttribute(down_mma,  cudaFuncAttributeMaxDynamicSharedMemorySize, smem_down);
    cudaFuncSetAttribute(final_mma, cudaFuncAttributeMaxDynamicSharedMemorySize, smem_final);

    conv3_kernel<<<dim3(256, 3), 256>>>(wsg, wsgh, wsu, wsuh, wsd, wsdh,
                                        SINTER * DIM / 8);
    router_kernel<<<T_TOK / 16, 256>>>(x, wg);
    group_kernel<<<NEXP, 1024>>>();
    up_mma<<<dim3(16, NEXP * 2 + SINTER / 128), 256, smem_up>>>(x, w1, w3);
    down_mma<<<dim3(16, NEXP, 2), 256, smem_down>>>(w2);
    final_mma<<<dim3(16, 2, KSPLIT), 256, smem_final>>>();
    reduce_kernel<<<T_TOK, 256>>>(out);
}

// round 16
// speedup vs baseline: 1.7689x; 1.1141x over previous
#include <cuda_runtime.h>
#include <cuda_fp16.h>
#include <math.h>
#include <stdint.h>

#define T_TOK   1024
#define DIM     512
#define INTER   256
#define SINTER  1024
#define NEXP    64
#define TOPK    6
#define KC      32
#define KSPLIT  4

// A smem: fp16 (single plane) as u32 (fp16x2); row stride 20 u32 = 80 B
#define AK2      20
#define APL      (64 * AK2)          // u32 per buffer = 1280
#define A_BYTES  (2 * APL * 4)       // both buffers = 10240 B

// B [n][k] fp32 (expert up): 256 rows, stride 40 floats
#define BF_ST   40
#define BF_FB   (256 * BF_ST)
// B [n][k] fp16 (shared up / final): 256 rows, stride 40 halves
#define BH_ST   40
#define BH_HB   (256 * BH_ST)
// B [k][n] fp32 (down): 32 rows, stride 260 floats
#define BKN_ST  260
#define BKN_FB  (32 * BKN_ST)

// ---------------- scratch (device globals; no allocation) ----------------
__device__ int      g_topk_idx[T_TOK * TOPK];
__device__ float    g_topk_w[T_TOK * TOPK];
__device__ int      g_counts[NEXP];
__device__ int      g_tok[NEXP * T_TOK];
__device__ int      g_tslot[NEXP * T_TOK];
__device__ float    g_tw[NEXP * T_TOK];
__device__ float    g_contrib[T_TOK * TOPK * DIM];
__device__ float    g_part[KSPLIT * T_TOK * DIM];
__device__ uint32_t g_he_hi[NEXP * T_TOK * (INTER / 2)];
__device__ uint32_t g_hs_hi[T_TOK * (SINTER / 2)];
// fp16 SHARED-expert weights only (6 MB; converted once per launch)
__device__ __align__(16) __half g_wsgh[SINTER * DIM];
__device__ __align__(16) __half g_wsuh[SINTER * DIM];
__device__ __align__(16) __half g_wsdh[DIM * SINTER];

// ---------------- helpers ----------------
__device__ __forceinline__ uint32_t h2bits(float a, float b) {
    __half2 h = __floats2half2_rn(a, b);
    return *reinterpret_cast<uint32_t*>(&h);
}
__device__ __forceinline__ void mma16(float c[4], const uint32_t a[4],
                                      uint32_t b0, uint32_t b1) {
    asm volatile(
        "mma.sync.aligned.m16n8k16.row.col.f32.f16.f16.f32 "
        "{%0,%1,%2,%3}, {%4,%5,%6,%7}, {%8,%9}, {%0,%1,%2,%3};"
        : "+f"(c[0]), "+f"(c[1]), "+f"(c[2]), "+f"(c[3])
        : "r"(a[0]), "r"(a[1]), "r"(a[2]), "r"(a[3]), "r"(b0), "r"(b1));
}
__device__ __forceinline__ void cp16(void* dst_smem, const void* src) {
    uint32_t d = (uint32_t)__cvta_generic_to_shared(dst_smem);
    asm volatile("cp.async.cg.shared.global [%0], [%1], 16;" :: "r"(d), "l"(src));
}
__device__ __forceinline__ void cpcommit() {
    asm volatile("cp.async.commit_group;" ::: "memory");
}
template <int N> __device__ __forceinline__ void cpwait() {
    asm volatile("cp.async.wait_group %0;" :: "n"(N) : "memory");
}
__device__ __forceinline__ uint32_t smaddr(const void* p) {
    return (uint32_t)__cvta_generic_to_shared(p);
}
__device__ __forceinline__ void ldsm4(uint32_t& r0, uint32_t& r1, uint32_t& r2,
                                      uint32_t& r3, uint32_t a) {
    asm volatile("ldmatrix.sync.aligned.m8n8.x4.shared.b16 {%0,%1,%2,%3}, [%4];"
                 : "=r"(r0), "=r"(r1), "=r"(r2), "=r"(r3) : "r"(a));
}

// ---------------- 0. shared-weight conversion fp32 -> fp16 ----------------
__global__ __launch_bounds__(256) void conv3_kernel(
    const float* __restrict__ s0, __half* __restrict__ d0,
    const float* __restrict__ s1, __half* __restrict__ d1,
    const float* __restrict__ s2, __half* __restrict__ d2, int n8)
{
    const float* s = (blockIdx.y == 0) ? s0 : (blockIdx.y == 1) ? s1 : s2;
    __half*      d = (blockIdx.y == 0) ? d0 : (blockIdx.y == 1) ? d1 : d2;
    int i = blockIdx.x * 256 + threadIdx.x;
    int stride = gridDim.x * 256;
    for (; i < n8; i += stride) {
        float4 v0 = ((const float4*)s)[2 * i];
        float4 v1 = ((const float4*)s)[2 * i + 1];
        __half2 h0 = __floats2half2_rn(v0.x, v0.y);
        __half2 h1 = __floats2half2_rn(v0.z, v0.w);
        __half2 h2 = __floats2half2_rn(v1.x, v1.y);
        __half2 h3 = __floats2half2_rn(v1.z, v1.w);
        uint4 o;
        o.x = *(uint32_t*)&h0; o.y = *(uint32_t*)&h1;
        o.z = *(uint32_t*)&h2; o.w = *(uint32_t*)&h3;
        ((uint4*)d)[i] = o;
    }
}

// ---------------- 1. router ----------------
__global__ __launch_bounds__(256) void router_kernel(
    const float* __restrict__ x, const float* __restrict__ wg)
{
    const int t0  = blockIdx.x * 16;
    const int tid = threadIdx.x;
    __shared__ float xs[16 * DIM];
    __shared__ float sc[16 * NEXP];

    for (int idx = tid; idx < 16 * DIM / 4; idx += 256)
        *(float4*)&xs[idx * 4] = *(const float4*)&x[(size_t)t0 * DIM + idx * 4];
    __syncthreads();

    int e  = tid & 63;
    int tg = tid >> 6;
    const float4* wr = (const float4*)(wg + (size_t)e * DIM);
    for (int tt = tg; tt < 16; tt += 4) {
        float acc = 0.f;
        #pragma unroll 4
        for (int d4 = 0; d4 < DIM / 4; d4++) {
            float4 w  = wr[d4];
            float4 xv = *(const float4*)&xs[tt * DIM + d4 * 4];
            acc = fmaf(w.x, xv.x, fmaf(w.y, xv.y, fmaf(w.z, xv.z, fmaf(w.w, xv.w, acc))));
        }
        sc[tt * NEXP + e] = acc;
    }
    __syncthreads();

    if (tid < 16) {
        float* s = &sc[tid * NEXP];
        float vals[TOPK]; int idx[TOPK];
        for (int k = 0; k < TOPK; k++) {
            float best = -INFINITY; int bi = 0;
            for (int ee = 0; ee < NEXP; ee++)
                if (s[ee] > best) { best = s[ee]; bi = ee; }
            vals[k] = best; idx[k] = bi; s[bi] = -INFINITY;
        }
        float mx = vals[0];
        float w6[TOPK]; float sum = 0.f;
        #pragma unroll
        for (int k = 0; k < TOPK; k++) { w6[k] = __expf(vals[k] - mx); sum += w6[k]; }
        float inv = 1.f / sum;
        int t = t0 + tid;
        #pragma unroll
        for (int k = 0; k < TOPK; k++) {
            g_topk_idx[t * TOPK + k] = idx[k];
            g_topk_w[t * TOPK + k]   = w6[k] * inv;
        }
    }
}

// ---------------- 2. deterministic grouping (ballot scan) ----------------
__global__ __launch_bounds__(1024) void group_kernel()
{
    int e = blockIdx.x;
    int t = threadIdx.x;
    int warp = t >> 5, lane = t & 31;
    int slot = -1;
    #pragma unroll
    for (int k = 0; k < TOPK; k++)
        if (g_topk_idx[t * TOPK + k] == e) slot = k;
    unsigned mask = __ballot_sync(0xffffffffu, slot >= 0);

    __shared__ int wbase[32];
    if (lane == 0) wbase[warp] = __popc(mask);
    __syncthreads();
    if (t < 32) {
        int v = wbase[t];
        int s = v;
        #pragma unroll
        for (int off = 1; off < 32; off <<= 1) {
            int u = __shfl_up_sync(0xffffffffu, s, off);
            if (t >= off) s += u;
        }
        wbase[t] = s - v;
        if (t == 31) g_counts[e] = s;
    }
    __syncthreads();
    if (slot >= 0) {
        int pos = wbase[warp] + __popc(mask & ((1u << lane) - 1u));
        g_tok[e * T_TOK + pos]   = t;
        g_tslot[e * T_TOK + pos] = slot;
        g_tw[e * T_TOK + pos]    = g_topk_w[t * TOPK + slot];
    }
}

// ---------------- 3. fused gate+up projection (experts + shared) ----------
// grid (16, NEXP*2 + SINTER/128)
__global__ __launch_bounds__(256, 2) void up_mma(const float* __restrict__ x,
    const float* __restrict__ w1, const float* __restrict__ w3)
{
    extern __shared__ __align__(16) char smc[];
    uint32_t* Au  = (uint32_t*)smc;              // [2 buf][64][AK2] fp16x2
    float*    Bf  = (float*)(smc + A_BYTES);     // expert: [2][256][BF_ST] fp32
    __half*   Bh  = (__half*)(smc + A_BYTES);    // shared: [2][256][BH_ST] fp16

    const int by = blockIdx.y;
    const bool is_shared = (by >= NEXP * 2);
    const int tid  = threadIdx.x;
    const int wid  = tid >> 5;
    const int lane = tid & 31;
    const int gid  = lane >> 2;
    const int l4   = lane & 3;
    const int m0   = blockIdx.x * 64;

    __shared__ int s_row[64];

    int e = 0, ncol0 = 0;
    const float  *Wgf = nullptr, *Wuf = nullptr;
    const __half *Wgh = nullptr, *Wuh = nullptr;
    if (is_shared) {
        int js = by - NEXP * 2;
        ncol0 = js * 128;
        Wgh = g_wsgh + (size_t)ncol0 * DIM;
        Wuh = g_wsuh + (size_t)ncol0 * DIM;
        if (tid < 64) s_row[tid] = m0 + tid;
    } else {
        e = by >> 1;
        int cnt = g_counts[e];
        if (m0 >= cnt) return;
        int mr = min(64, cnt - m0);
        int j  = by & 1;
        ncol0 = j * 128;
        Wgf = w1 + (size_t)e * INTER * DIM + (size_t)ncol0 * DIM;
        Wuf = w3 + (size_t)e * INTER * DIM + (size_t)ncol0 * DIM;
        if (tid < 64) s_row[tid] = g_tok[e * T_TOK + m0 + ((tid < mr) ? tid : 0)];
    }
    __syncthreads();

    const int ar  = tid >> 2;
    const int acb = (tid & 3) * 4;
    const float* xrow = x + (size_t)s_row[ar] * DIM;

    const uint32_t a_base = smaddr(Au) + (lane & 15) * 80 + (lane >> 4) * 16;
    const uint32_t bh_base = smaddr(Bh) + (((lane >> 4) & 1) * 8 + (lane & 7)) * 80
                                         + ((lane >> 3) & 1) * 16;
    const int nn[4] = { wid * 16 + gid, wid * 16 + 8 + gid,
                        128 + wid * 16 + gid, 128 + wid * 16 + 8 + gid };

    float c[4][4][4];   // ct 0..1 = gate cols, ct 2..3 = up cols
    #pragma unroll
    for (int i = 0; i < 4; i++)
        #pragma unroll
        for (int j = 0; j < 4; j++)
            #pragma unroll
            for (int q = 0; q < 4; q++) c[i][j][q] = 0.f;

    float4 pa0 = *(const float4*)(xrow + acb * 2);
    float4 pa1 = *(const float4*)(xrow + acb * 2 + 4);

    const int NCH = DIM / KC;   // 16

    if (!is_shared) {
        // ---- expert path: B fp32, cvt at fragment build ----
        #pragma unroll
        for (int j = 0; j < 8; j++) {
            int idx = tid + 256 * j;
            int row = idx >> 3, col = (idx & 7) * 4;
            const float* src = (row < 128) ? (Wgf + (size_t)row * DIM + col)
                                           : (Wuf + (size_t)(row - 128) * DIM + col);
            cp16(&Bf[row * BF_ST + col], src);
        }
        cpcommit();
        for (int kc = 0; kc < NCH; kc++) {
            int st = kc & 1;
            {
                uint32_t h0 = h2bits(pa0.x, pa0.y);
                uint32_t h1 = h2bits(pa0.z, pa0.w);
                uint32_t h2 = h2bits(pa1.x, pa1.y);
                uint32_t h3 = h2bits(pa1.z, pa1.w);
                uint32_t* d = Au + st * APL + ar * AK2 + acb;
                *(uint4*)d = make_uint4(h0, h1, h2, h3);
            }
            cpwait<0>();
            __syncthreads();
            if (kc < NCH - 1) {
                int kb = (kc + 1) * KC;
                int sn = st ^ 1;
                pa0 = *(const float4*)(xrow + kb + acb * 2);
                pa1 = *(const float4*)(xrow + kb + acb * 2 + 4);
                #pragma unroll
                for (int j = 0; j < 8; j++) {
                    int idx = tid + 256 * j;
                    int row = idx >> 3, col = (idx & 7) * 4;
                    const float* src = (row < 128) ? (Wgf + (size_t)row * DIM + kb + col)
                                                   : (Wuf + (size_t)(row - 128) * DIM + kb + col);
                    cp16(&Bf[sn * BF_FB + row * BF_ST + col], src);
                }
                cpcommit();
            }
            uint32_t ab = a_base + st * (APL * 4);
            const float* Bsb = Bf + st * BF_FB;
            #pragma unroll
            for (int ks = 0; ks < 2; ks++) {
                uint32_t bq[8];
                #pragma unroll
                for (int ct = 0; ct < 4; ct++) {
                    const float* bp = Bsb + nn[ct] * BF_ST + ks * 16 + 2 * l4;
                    float2 v0 = *(const float2*)bp;
                    float2 v1 = *(const float2*)(bp + 8);
                    bq[2 * ct]     = h2bits(v0.x, v0.y);
                    bq[2 * ct + 1] = h2bits(v1.x, v1.y);
                }
                uint32_t ah[4][4];
                #pragma unroll
                for (int rt = 0; rt < 4; rt++)
                    ldsm4(ah[rt][0], ah[rt][1], ah[rt][2], ah[rt][3],
                          ab + rt * 1280 + ks * 32);
                #pragma unroll
                for (int ct = 0; ct < 4; ct++)
                    #pragma unroll
                    for (int rt = 0; rt < 4; rt++)
                        mma16(c[rt][ct], ah[rt], bq[2 * ct], bq[2 * ct + 1]);
            }
        }
    } else {
        // ---- shared path: B fp16, ldmatrix ----
        #pragma unroll
        for (int j = 0; j < 4; j++) {
            int idx = tid + 256 * j;
            int row = idx >> 2, seg = (idx & 3) * 8;
            const __half* src = (row < 128) ? (Wgh + (size_t)row * DIM + seg)
                                            : (Wuh + (size_t)(row - 128) * DIM + seg);
            cp16(Bh + row * BH_ST + seg, src);
        }
        cpcommit();
        for (int kc = 0; kc < NCH; kc++) {
            int st = kc & 1;
            {
                uint32_t h0 = h2bits(pa0.x, pa0.y);
                uint32_t h1 = h2bits(pa0.z, pa0.w);
                uint32_t h2 = h2bits(pa1.x, pa1.y);
                uint32_t h3 = h2bits(pa1.z, pa1.w);
                uint32_t* d = Au + st * APL + ar * AK2 + acb;
                *(uint4*)d = make_uint4(h0, h1, h2, h3);
            }
            cpwait<0>();
            __syncthreads();
            if (kc < NCH - 1) {
                int kb = (kc + 1) * KC;
                int sn = st ^ 1;
                pa0 = *(const float4*)(xrow + kb + acb * 2);
                pa1 = *(const float4*)(xrow + kb + acb * 2 + 4);
                #pragma unroll
                for (int j = 0; j < 4; j++) {
                    int idx = tid + 256 * j;
                    int row = idx >> 2, seg = (idx & 3) * 8;
                    const __half* src = (row < 128) ? (Wgh + (size_t)row * DIM + kb + seg)
                                                    : (Wuh + (size_t)(row - 128) * DIM + kb + seg);
                    cp16(Bh + sn * BH_HB + row * BH_ST + seg, src);
                }
                cpcommit();
            }
            uint32_t ab = a_base + st * (APL * 4);
            uint32_t bb = bh_base + st * (BH_HB * 2);
            #pragma unroll
            for (int ks = 0; ks < 2; ks++) {
                uint32_t bq[8];
                ldsm4(bq[0], bq[1], bq[2], bq[3], bb + (wid * 16) * 80 + ks * 32);
                ldsm4(bq[4], bq[5], bq[6], bq[7], bb + (128 + wid * 16) * 80 + ks * 32);
                uint32_t ah[4][4];
                #pragma unroll
                for (int rt = 0; rt < 4; rt++)
                    ldsm4(ah[rt][0], ah[rt][1], ah[rt][2], ah[rt][3],
                          ab + rt * 1280 + ks * 32);
                #pragma unroll
                for (int ct = 0; ct < 4; ct++)
                    #pragma unroll
                    for (int rt = 0; rt < 4; rt++)
                        mma16(c[rt][ct], ah[rt], bq[2 * ct], bq[2 * ct + 1]);
            }
        }
    }

    // epilogue: h = silu(gate)*up in regs -> fp16 -> global
    #pragma unroll
    for (int rt = 0; rt < 4; rt++) {
        #pragma unroll
        for (int ct = 0; ct < 2; ct++) {
            int col = ncol0 + wid * 16 + ct * 8 + 2 * l4;
            #pragma unroll
            for (int half = 0; half < 2; half++) {
                int r = rt * 16 + gid + half * 8;
                float g0 = c[rt][ct][half * 2],     u0 = c[rt][ct + 2][half * 2];
                float g1 = c[rt][ct][half * 2 + 1], u1 = c[rt][ct + 2][half * 2 + 1];
                float h0 = (g0 / (1.f + __expf(-g0))) * u0;
                float h1 = (g1 / (1.f + __expf(-g1))) * u1;
                uint32_t hh = h2bits(h0, h1);
                if (is_shared) {
                    size_t gi = (size_t)(m0 + r) * (SINTER / 2) + (col >> 1);
                    g_hs_hi[gi] = hh;
                } else {
                    size_t gi = ((size_t)e * T_TOK + m0 + r) * (INTER / 2) + (col >> 1);
                    g_he_hi[gi] = hh;
                }
            }
        }
    }
}

// ---------------- 4. expert down-projection ----------------
// grid (16, NEXP, 2); B fp32 [k][n], cvt at fragment build; A ldmatrix
__global__ __launch_bounds__(256, 2) void down_mma(const float* __restrict__ w2)
{
    extern __shared__ __align__(16) char smc[];
    uint32_t* Au = (uint32_t*)smc;               // [2][64][AK2]
    float*    Bs = (float*)(smc + A_BYTES);      // [2][32][BKN_ST] fp32 [k][n]

    const int e  = blockIdx.y;
    const int cnt = g_counts[e];
    const int m0 = blockIdx.x * 64;
    if (m0 >= cnt) return;
    const int mr = min(64, cnt - m0);
    const int n0 = blockIdx.z * 256;

    const int tid  = threadIdx.x;
    const int wid  = tid >> 5;
    const int lane = tid & 31;
    const int gid  = lane >> 2;
    const int l4   = lane & 3;

    __shared__ int   s_tok[64];
    __shared__ int   s_slot[64];
    __shared__ float s_w[64];
    if (tid < 64) {
        int mm = (tid < mr) ? tid : 0;
        s_tok[tid]  = g_tok[e * T_TOK + m0 + mm];
        s_slot[tid] = g_tslot[e * T_TOK + m0 + mm];
        s_w[tid]    = g_tw[e * T_TOK + m0 + mm];
    }

    const uint32_t* hhi = g_he_hi + ((size_t)e * T_TOK + m0) * (INTER / 2);
    const float* w2base = w2 + (size_t)e * INTER * DIM + n0;

    const uint32_t a_base = smaddr(Au) + (lane & 15) * 80 + (lane >> 4) * 16;
    const int nn[4] = { wid * 32 + gid, wid * 32 + 8 + gid,
                        wid * 32 + 16 + gid, wid * 32 + 24 + gid };

    float c[4][4][4];
    #pragma unroll
    for (int i = 0; i < 4; i++)
        #pragma unroll
        for (int j = 0; j < 4; j++)
            #pragma unroll
            for (int q = 0; q < 4; q++) c[i][j][q] = 0.f;

    {
        {
            int row = tid >> 2, seg = (tid & 3) * 4;
            cp16(Au + row * AK2 + seg, hhi + (size_t)row * (INTER / 2) + seg);
        }
        #pragma unroll
        for (int j = 0; j < 8; j++) {
            int idx = tid + 256 * j;
            int kr = idx >> 6, nc = (idx & 63) * 4;
            cp16(&Bs[kr * BKN_ST + nc], w2base + (size_t)kr * DIM + nc);
        }
        cpcommit();
    }
    const int NCH = INTER / KC;   // 8
    for (int kc = 0; kc < NCH; kc++) {
        int st = kc & 1;
        cpwait<0>();
        __syncthreads();
        if (kc < NCH - 1) {
            int kb2 = (kc + 1) * 16;
            int kb  = (kc + 1) * KC;
            int sn = st ^ 1;
            {
                int row = tid >> 2, seg = (tid & 3) * 4;
                cp16(Au + sn * APL + row * AK2 + seg,
                     hhi + (size_t)row * (INTER / 2) + kb2 + seg);
            }
            #pragma unroll
            for (int j = 0; j < 8; j++) {
                int idx = tid + 256 * j;
                int kr = idx >> 6, nc = (idx & 63) * 4;
                cp16(&Bs[sn * BKN_FB + kr * BKN_ST + nc],
                     w2base + (size_t)(kb + kr) * DIM + nc);
            }
            cpcommit();
        }
        uint32_t ab = a_base + st * (APL * 4);
        const float* Bsb = Bs + st * BKN_FB;
        #pragma unroll
        for (int ks = 0; ks < 2; ks++) {
            uint32_t bq[8];
            #pragma unroll
            for (int ct = 0; ct < 4; ct++) {
                int n = nn[ct];
                int kk = ks * 16 + 2 * l4;
                bq[2 * ct]     = h2bits(Bsb[kk * BKN_ST + n],       Bsb[(kk + 1) * BKN_ST + n]);
                bq[2 * ct + 1] = h2bits(Bsb[(kk + 8) * BKN_ST + n], Bsb[(kk + 9) * BKN_ST + n]);
            }
            uint32_t ah[4][4];
            #pragma unroll
            for (int rt = 0; rt < 4; rt++)
                ldsm4(ah[rt][0], ah[rt][1], ah[rt][2], ah[rt][3],
                      ab + rt * 1280 + ks * 32);
            #pragma unroll
            for (int ct = 0; ct < 4; ct++)
                #pragma unroll
                for (int rt = 0; rt < 4; rt++)
                    mma16(c[rt][ct], ah[rt], bq[2 * ct], bq[2 * ct + 1]);
        }
    }

    #pragma unroll
    for (int rt = 0; rt < 4; rt++) {
        #pragma unroll
        for (int ct = 0; ct < 4; ct++) {
            int col = n0 + wid * 32 + ct * 8 + 2 * l4;
            #pragma unroll
            for (int half = 0; half < 2; half++) {
                int r = rt * 16 + gid + half * 8;
                if (r < mr) {
                    size_t base = ((size_t)(s_tok[r] * TOPK + s_slot[r])) * DIM + col;
                    float w = s_w[r];
                    *(float2*)&g_contrib[base] =
                        make_float2(w * c[rt][ct][half * 2], w * c[rt][ct][half * 2 + 1]);
                }
            }
        }
    }
}

// ---------------- 5. final GEMM split-K(4): part = H @ Wsd^T (fp16 B) ------
// grid (16, 2, KSPLIT)
__global__ __launch_bounds__(256, 2) void final_mma()
{
    extern __shared__ __align__(16) char smc[];
    uint32_t* Au = (uint32_t*)smc;               // [2][64][AK2]
    __half*   Bs = (__half*)(smc + A_BYTES);     // [2][256][BH_ST]

    const int m0 = blockIdx.x * 64;
    const int n0 = blockIdx.y * 256;
    const int k0 = blockIdx.z * 256;
    const int k02 = k0 / 2;
    const int tid  = threadIdx.x;
    const int wid  = tid >> 5;
    const int lane = tid & 31;
    const int gid  = lane >> 2;
    const int l4   = lane & 3;

    const uint32_t a_base = smaddr(Au) + (lane & 15) * 80 + (lane >> 4) * 16;
    const uint32_t b_base = smaddr(Bs) + (((lane >> 4) & 1) * 8 + (lane & 7)) * 80
                                        + ((lane >> 3) & 1) * 16;

    float c[4][4][4];
    #pragma unroll
    for (int i = 0; i < 4; i++)
        #pragma unroll
        for (int j = 0; j < 4; j++)
            #pragma unroll
            for (int q = 0; q < 4; q++) c[i][j][q] = 0.f;

    {
        {
            int row = tid >> 2, seg = (tid & 3) * 4;
            cp16(Au + row * AK2 + seg,
                 g_hs_hi + (size_t)(m0 + row) * (SINTER / 2) + k02 + seg);
        }
        #pragma unroll
        for (int j = 0; j < 4; j++) {
            int idx = tid + 256 * j;
            int row = idx >> 2, seg = (idx & 3) * 8;
            cp16(Bs + row * BH_ST + seg,
                 g_wsdh + (size_t)(n0 + row) * SINTER + k0 + seg);
        }
        cpcommit();
    }
    const int NCH = 256 / KC;   // 8
    for (int kc = 0; kc < NCH; kc++) {
        int st = kc & 1;
        cpwait<0>();
        __syncthreads();
        if (kc < NCH - 1) {
            int kb  = (kc + 1) * KC;
            int kb2 = (kc + 1) * 16;
            int sn = st ^ 1;
            {
                int row = tid >> 2, seg = (tid & 3) * 4;
                cp16(Au + sn * APL + row * AK2 + seg,
                     g_hs_hi + (size_t)(m0 + row) * (SINTER / 2) + k02 + kb2 + seg);
            }
            #pragma unroll
            for (int j = 0; j < 4; j++) {
                int idx = tid + 256 * j;
                int row = idx >> 2, seg = (idx & 3) * 8;
                cp16(Bs + sn * BH_HB + row * BH_ST + seg,
                     g_wsdh + (size_t)(n0 + row) * SINTER + k0 + kb + seg);
            }
            cpcommit();
        }
        uint32_t ab = a_base + st * (APL * 4);
        uint32_t bb = b_base + st * (BH_HB * 2);
        #pragma unroll
        for (int ks = 0; ks < 2; ks++) {
            uint32_t bq[8];
            ldsm4(bq[0], bq[1], bq[2], bq[3], bb + (wid * 32) * 80 + ks * 32);
            ldsm4(bq[4], bq[5], bq[6], bq[7], bb + (wid * 32 + 16) * 80 + ks * 32);
            uint32_t ah[4][4];
            #pragma unroll
            for (int rt = 0; rt < 4; rt++)
                ldsm4(ah[rt][0], ah[rt][1], ah[rt][2], ah[rt][3],
                      ab + rt * 1280 + ks * 32);
            #pragma unroll
            for (int ct = 0; ct < 4; ct++)
                #pragma unroll
                for (int rt = 0; rt < 4; rt++)
                    mma16(c[rt][ct], ah[rt], bq[2 * ct], bq[2 * ct + 1]);
        }
    }

    #pragma unroll
    for (int rt = 0; rt < 4; rt++) {
        #pragma unroll
        for (int ct = 0; ct < 4; ct++) {
            int col = n0 + wid * 32 + ct * 8 + 2 * l4;
            int r0 = m0 + rt * 16 + gid, r1 = r0 + 8;
            *(float2*)&g_part[((size_t)blockIdx.z * T_TOK + r0) * DIM + col]
                = make_float2(c[rt][ct][0], c[rt][ct][1]);
            *(float2*)&g_part[((size_t)blockIdx.z * T_TOK + r1) * DIM + col]
                = make_float2(c[rt][ct][2], c[rt][ct][3]);
        }
    }
}

// ---------------- 6. reduce ----------------
__global__ __launch_bounds__(256) void reduce_kernel(float* __restrict__ out)
{
    int t = blockIdx.x;
    #pragma unroll
    for (int h = 0; h < 2; h++) {
        int d = threadIdx.x + h * 256;
        float v = 0.f;
        #pragma unroll
        for (int z = 0; z < KSPLIT; z++)
            v += g_part[((size_t)z * T_TOK + t) * DIM + d];
        #pragma unroll
        for (int k = 0; k < TOPK; k++)
            v += g_contrib[((size_t)t * TOPK + k) * DIM + d];
        out[(size_t)t * DIM + d] = v;
    }
}

// ---------------- launcher ----------------
extern "C" void kernel_launch(void* const* d_in, const int* in_sizes, int n_in,
                              void* d_out, int out_size)
{
    const float* x   = (const float*)d_in[0];
    const float* wg  = (const float*)d_in[1];
    const float* w1  = (const float*)d_in[2];
    const float* w2  = (const float*)d_in[3];
    const float* w3  = (const float*)d_in[4];
    const float* wsg = (const float*)d_in[5];
    const float* wsu = (const float*)d_in[6];
    const float* wsd = (const float*)d_in[7];
    float* out = (float*)d_out;

    __half *wsgh, *wsuh, *wsdh;
    cudaGetSymbolAddress((void**)&wsgh, g_wsgh);
    cudaGetSymbolAddress((void**)&wsuh, g_wsuh);
    cudaGetSymbolAddress((void**)&wsdh, g_wsdh);

    const int smem_up    = A_BYTES + 2 * BF_FB * 4;      // 10240 + 81920 = 92160
    const int smem_down  = A_BYTES + 2 * BKN_FB * 4;     // 10240 + 66560 = 76800
    const int smem_final = A_BYTES + 2 * BH_HB * 2;      // 10240 + 40960 = 51200

    cudaFuncSetAttribute(up_mma,    cudaFuncAttributeMaxDynamicSharedMemorySize, smem_up);
    cudaFuncSetAttribute(down_mma,  cudaFuncAttributeMaxDynamicSharedMemorySize, smem_down);
    cudaFuncSetAttribute(final_mma, cudaFuncAttributeMaxDynamicSharedMemorySize, smem_final);

    conv3_kernel<<<dim3(256, 3), 256>>>(wsg, wsgh, wsu, wsuh, wsd, wsdh,
                                        SINTER * DIM / 8);
    router_kernel<<<T_TOK / 16, 256>>>(x, wg);
    group_kernel<<<NEXP, 1024>>>();
    up_mma<<<dim3(16, NEXP * 2 + SINTER / 128), 256, smem_up>>>(x, w1, w3);
    down_mma<<<dim3(16, NEXP, 2), 256, smem_down>>>(w2);
    final_mma<<<dim3(16, 2, KSPLIT), 256, smem_final>>>();
    reduce_kernel<<<T_TOK, 256>>>(out);
}

// round 17
// speedup vs baseline: 1.7958x; 1.0152x over previous
#include <cuda_runtime.h>
#include <cuda_fp16.h>
#include <math.h>
#include <stdint.h>

#define T_TOK   1024
#define DIM     512
#define INTER   256
#define SINTER  1024
#define NEXP    64
#define TOPK    6
#define KC      32
#define KSPLIT  2

// A smem: fp16 (single plane) as u32 (fp16x2); row stride 20 u32 = 80 B
#define AK2      20
#define APL      (64 * AK2)          // u32 per buffer = 1280
#define A_BYTES  (2 * APL * 4)       // both buffers = 10240 B

// B [n][k] fp32 (expert up): 256 rows, stride 40 floats
#define BF_ST   40
#define BF_FB   (256 * BF_ST)
// B [n][k] fp16 (shared up / final): 256 rows, stride 40 halves
#define BH_ST   40
#define BH_HB   (256 * BH_ST)
// B [k][n] fp32 (down): 32 rows, stride 260 floats
#define BKN_ST  260
#define BKN_FB  (32 * BKN_ST)

// ---------------- scratch (device globals; no allocation) ----------------
__device__ int      g_topk_idx[T_TOK * TOPK];
__device__ float    g_topk_w[T_TOK * TOPK];
__device__ int      g_counts[NEXP];
__device__ int      g_tok[NEXP * T_TOK];
__device__ int      g_tslot[NEXP * T_TOK];
__device__ float    g_tw[NEXP * T_TOK];
__device__ float    g_contrib[T_TOK * TOPK * DIM];
__device__ float    g_part[KSPLIT * T_TOK * DIM];
__device__ uint32_t g_he_hi[NEXP * T_TOK * (INTER / 2)];
__device__ uint32_t g_hs_hi[T_TOK * (SINTER / 2)];
// fp16 SHARED-expert weights only (6 MB; converted once per launch)
__device__ __align__(16) __half g_wsgh[SINTER * DIM];
__device__ __align__(16) __half g_wsuh[SINTER * DIM];
__device__ __align__(16) __half g_wsdh[DIM * SINTER];

// ---------------- helpers ----------------
__device__ __forceinline__ uint32_t h2bits(float a, float b) {
    __half2 h = __floats2half2_rn(a, b);
    return *reinterpret_cast<uint32_t*>(&h);
}
__device__ __forceinline__ void mma16(float c[4], const uint32_t a[4],
                                      uint32_t b0, uint32_t b1) {
    asm volatile(
        "mma.sync.aligned.m16n8k16.row.col.f32.f16.f16.f32 "
        "{%0,%1,%2,%3}, {%4,%5,%6,%7}, {%8,%9}, {%0,%1,%2,%3};"
        : "+f"(c[0]), "+f"(c[1]), "+f"(c[2]), "+f"(c[3])
        : "r"(a[0]), "r"(a[1]), "r"(a[2]), "r"(a[3]), "r"(b0), "r"(b1));
}
__device__ __forceinline__ void cp16(void* dst_smem, const void* src) {
    uint32_t d = (uint32_t)__cvta_generic_to_shared(dst_smem);
    asm volatile("cp.async.cg.shared.global [%0], [%1], 16;" :: "r"(d), "l"(src));
}
__device__ __forceinline__ void cpcommit() {
    asm volatile("cp.async.commit_group;" ::: "memory");
}
template <int N> __device__ __forceinline__ void cpwait() {
    asm volatile("cp.async.wait_group %0;" :: "n"(N) : "memory");
}
__device__ __forceinline__ uint32_t smaddr(const void* p) {
    return (uint32_t)__cvta_generic_to_shared(p);
}
__device__ __forceinline__ void ldsm4(uint32_t& r0, uint32_t& r1, uint32_t& r2,
                                      uint32_t& r3, uint32_t a) {
    asm volatile("ldmatrix.sync.aligned.m8n8.x4.shared.b16 {%0,%1,%2,%3}, [%4];"
                 : "=r"(r0), "=r"(r1), "=r"(r2), "=r"(r3) : "r"(a));
}

// ---------------- 0+1. fused: shared-weight conv (y<3) + router (y==3) ----
__global__ __launch_bounds__(256) void pre_kernel(
    const float* __restrict__ wsg, const float* __restrict__ wsu,
    const float* __restrict__ wsd,
    const float* __restrict__ x, const float* __restrict__ wg)
{
    const int part = blockIdx.y;
    if (part < 3) {
        const float* s = (part == 0) ? wsg : (part == 1) ? wsu : wsd;
        __half*      d = (part == 0) ? g_wsgh : (part == 1) ? g_wsuh : g_wsdh;
        int n8 = SINTER * DIM / 8;
        int i = blockIdx.x * 256 + threadIdx.x;
        int stride = gridDim.x * 256;
        for (; i < n8; i += stride) {
            float4 v0 = ((const float4*)s)[2 * i];
            float4 v1 = ((const float4*)s)[2 * i + 1];
            __half2 h0 = __floats2half2_rn(v0.x, v0.y);
            __half2 h1 = __floats2half2_rn(v0.z, v0.w);
            __half2 h2 = __floats2half2_rn(v1.x, v1.y);
            __half2 h3 = __floats2half2_rn(v1.z, v1.w);
            uint4 o;
            o.x = *(uint32_t*)&h0; o.y = *(uint32_t*)&h1;
            o.z = *(uint32_t*)&h2; o.w = *(uint32_t*)&h3;
            ((uint4*)d)[i] = o;
        }
        return;
    }
    // ---- router path ----
    if (blockIdx.x >= T_TOK / 16) return;
    const int t0  = blockIdx.x * 16;
    const int tid = threadIdx.x;
    __shared__ float xs[16 * DIM];
    __shared__ float sc[16 * NEXP];

    for (int idx = tid; idx < 16 * DIM / 4; idx += 256)
        *(float4*)&xs[idx * 4] = *(const float4*)&x[(size_t)t0 * DIM + idx * 4];
    __syncthreads();

    int e  = tid & 63;
    int tg = tid >> 6;
    const float4* wr = (const float4*)(wg + (size_t)e * DIM);
    for (int tt = tg; tt < 16; tt += 4) {
        float acc = 0.f;
        #pragma unroll 4
        for (int d4 = 0; d4 < DIM / 4; d4++) {
            float4 w  = wr[d4];
            float4 xv = *(const float4*)&xs[tt * DIM + d4 * 4];
            acc = fmaf(w.x, xv.x, fmaf(w.y, xv.y, fmaf(w.z, xv.z, fmaf(w.w, xv.w, acc))));
        }
        sc[tt * NEXP + e] = acc;
    }
    __syncthreads();

    if (tid < 16) {
        float* s = &sc[tid * NEXP];
        float vals[TOPK]; int idx[TOPK];
        for (int k = 0; k < TOPK; k++) {
            float best = -INFINITY; int bi = 0;
            for (int ee = 0; ee < NEXP; ee++)
                if (s[ee] > best) { best = s[ee]; bi = ee; }
            vals[k] = best; idx[k] = bi; s[bi] = -INFINITY;
        }
        float mx = vals[0];
        float w6[TOPK]; float sum = 0.f;
        #pragma unroll
        for (int k = 0; k < TOPK; k++) { w6[k] = __expf(vals[k] - mx); sum += w6[k]; }
        float inv = 1.f / sum;
        int t = t0 + tid;
        #pragma unroll
        for (int k = 0; k < TOPK; k++) {
            g_topk_idx[t * TOPK + k] = idx[k];
            g_topk_w[t * TOPK + k]   = w6[k] * inv;
        }
    }
}

// ---------------- 2. deterministic grouping (ballot scan) ----------------
__global__ __launch_bounds__(1024) void group_kernel()
{
    int e = blockIdx.x;
    int t = threadIdx.x;
    int warp = t >> 5, lane = t & 31;
    int slot = -1;
    #pragma unroll
    for (int k = 0; k < TOPK; k++)
        if (g_topk_idx[t * TOPK + k] == e) slot = k;
    unsigned mask = __ballot_sync(0xffffffffu, slot >= 0);

    __shared__ int wbase[32];
    if (lane == 0) wbase[warp] = __popc(mask);
    __syncthreads();
    if (t < 32) {
        int v = wbase[t];
        int s = v;
        #pragma unroll
        for (int off = 1; off < 32; off <<= 1) {
            int u = __shfl_up_sync(0xffffffffu, s, off);
            if (t >= off) s += u;
        }
        wbase[t] = s - v;
        if (t == 31) g_counts[e] = s;
    }
    __syncthreads();
    if (slot >= 0) {
        int pos = wbase[warp] + __popc(mask & ((1u << lane) - 1u));
        g_tok[e * T_TOK + pos]   = t;
        g_tslot[e * T_TOK + pos] = slot;
        g_tw[e * T_TOK + pos]    = g_topk_w[t * TOPK + slot];
    }
}

// ---------------- 3. fused gate+up projection (experts + shared) ----------
// grid (16, NEXP*2 + SINTER/128)
__global__ __launch_bounds__(256, 2) void up_mma(const float* __restrict__ x,
    const float* __restrict__ w1, const float* __restrict__ w3)
{
    extern __shared__ __align__(16) char smc[];
    uint32_t* Au  = (uint32_t*)smc;              // [2 buf][64][AK2] fp16x2
    float*    Bf  = (float*)(smc + A_BYTES);     // expert: [2][256][BF_ST] fp32
    __half*   Bh  = (__half*)(smc + A_BYTES);    // shared: [2][256][BH_ST] fp16

    const int by = blockIdx.y;
    const bool is_shared = (by >= NEXP * 2);
    const int tid  = threadIdx.x;
    const int wid  = tid >> 5;
    const int lane = tid & 31;
    const int gid  = lane >> 2;
    const int l4   = lane & 3;
    const int m0   = blockIdx.x * 64;

    __shared__ int s_row[64];

    int e = 0, ncol0 = 0;
    const float  *Wgf = nullptr, *Wuf = nullptr;
    const __half *Wgh = nullptr, *Wuh = nullptr;
    if (is_shared) {
        int js = by - NEXP * 2;
        ncol0 = js * 128;
        Wgh = g_wsgh + (size_t)ncol0 * DIM;
        Wuh = g_wsuh + (size_t)ncol0 * DIM;
        if (tid < 64) s_row[tid] = m0 + tid;
    } else {
        e = by >> 1;
        int cnt = g_counts[e];
        if (m0 >= cnt) return;
        int mr = min(64, cnt - m0);
        int j  = by & 1;
        ncol0 = j * 128;
        Wgf = w1 + (size_t)e * INTER * DIM + (size_t)ncol0 * DIM;
        Wuf = w3 + (size_t)e * INTER * DIM + (size_t)ncol0 * DIM;
        if (tid < 64) s_row[tid] = g_tok[e * T_TOK + m0 + ((tid < mr) ? tid : 0)];
    }
    __syncthreads();

    const int ar  = tid >> 2;
    const int acb = (tid & 3) * 4;
    const float* xrow = x + (size_t)s_row[ar] * DIM;

    const uint32_t a_base = smaddr(Au) + (lane & 15) * 80 + (lane >> 4) * 16;
    const uint32_t bh_base = smaddr(Bh) + (((lane >> 4) & 1) * 8 + (lane & 7)) * 80
                                         + ((lane >> 3) & 1) * 16;
    const int nn[4] = { wid * 16 + gid, wid * 16 + 8 + gid,
                        128 + wid * 16 + gid, 128 + wid * 16 + 8 + gid };

    float c[4][4][4];   // ct 0..1 = gate cols, ct 2..3 = up cols
    #pragma unroll
    for (int i = 0; i < 4; i++)
        #pragma unroll
        for (int j = 0; j < 4; j++)
            #pragma unroll
            for (int q = 0; q < 4; q++) c[i][j][q] = 0.f;

    float4 pa0 = *(const float4*)(xrow + acb * 2);
    float4 pa1 = *(const float4*)(xrow + acb * 2 + 4);

    const int NCH = DIM / KC;   // 16

    if (!is_shared) {
        // ---- expert path: B fp32, cvt at fragment build ----
        #pragma unroll
        for (int j = 0; j < 8; j++) {
            int idx = tid + 256 * j;
            int row = idx >> 3, col = (idx & 7) * 4;
            const float* src = (row < 128) ? (Wgf + (size_t)row * DIM + col)
                                           : (Wuf + (size_t)(row - 128) * DIM + col);
            cp16(&Bf[row * BF_ST + col], src);
        }
        cpcommit();
        for (int kc = 0; kc < NCH; kc++) {
            int st = kc & 1;
            {
                uint32_t h0 = h2bits(pa0.x, pa0.y);
                uint32_t h1 = h2bits(pa0.z, pa0.w);
                uint32_t h2 = h2bits(pa1.x, pa1.y);
                uint32_t h3 = h2bits(pa1.z, pa1.w);
                uint32_t* d = Au + st * APL + ar * AK2 + acb;
                *(uint4*)d = make_uint4(h0, h1, h2, h3);
            }
            cpwait<0>();
            __syncthreads();
            if (kc < NCH - 1) {
                int kb = (kc + 1) * KC;
                int sn = st ^ 1;
                pa0 = *(const float4*)(xrow + kb + acb * 2);
                pa1 = *(const float4*)(xrow + kb + acb * 2 + 4);
                #pragma unroll
                for (int j = 0; j < 8; j++) {
                    int idx = tid + 256 * j;
                    int row = idx >> 3, col = (idx & 7) * 4;
                    const float* src = (row < 128) ? (Wgf + (size_t)row * DIM + kb + col)
                                                   : (Wuf + (size_t)(row - 128) * DIM + kb + col);
                    cp16(&Bf[sn * BF_FB + row * BF_ST + col], src);
                }
                cpcommit();
            }
            uint32_t ab = a_base + st * (APL * 4);
            const float* Bsb = Bf + st * BF_FB;
            #pragma unroll
            for (int ks = 0; ks < 2; ks++) {
                uint32_t bq[8];
                #pragma unroll
                for (int ct = 0; ct < 4; ct++) {
                    const float* bp = Bsb + nn[ct] * BF_ST + ks * 16 + 2 * l4;
                    float2 v0 = *(const float2*)bp;
                    float2 v1 = *(const float2*)(bp + 8);
                    bq[2 * ct]     = h2bits(v0.x, v0.y);
                    bq[2 * ct + 1] = h2bits(v1.x, v1.y);
                }
                uint32_t ah[4][4];
                #pragma unroll
                for (int rt = 0; rt < 4; rt++)
                    ldsm4(ah[rt][0], ah[rt][1], ah[rt][2], ah[rt][3],
                          ab + rt * 1280 + ks * 32);
                #pragma unroll
                for (int ct = 0; ct < 4; ct++)
                    #pragma unroll
                    for (int rt = 0; rt < 4; rt++)
                        mma16(c[rt][ct], ah[rt], bq[2 * ct], bq[2 * ct + 1]);
            }
        }
    } else {
        // ---- shared path: B fp16, ldmatrix ----
        #pragma unroll
        for (int j = 0; j < 4; j++) {
            int idx = tid + 256 * j;
            int row = idx >> 2, seg = (idx & 3) * 8;
            const __half* src = (row < 128) ? (Wgh + (size_t)row * DIM + seg)
                                            : (Wuh + (size_t)(row - 128) * DIM + seg);
            cp16(Bh + row * BH_ST + seg, src);
        }
        cpcommit();
        for (int kc = 0; kc < NCH; kc++) {
            int st = kc & 1;
            {
                uint32_t h0 = h2bits(pa0.x, pa0.y);
                uint32_t h1 = h2bits(pa0.z, pa0.w);
                uint32_t h2 = h2bits(pa1.x, pa1.y);
                uint32_t h3 = h2bits(pa1.z, pa1.w);
                uint32_t* d = Au + st * APL + ar * AK2 + acb;
                *(uint4*)d = make_uint4(h0, h1, h2, h3);
            }
            cpwait<0>();
            __syncthreads();
            if (kc < NCH - 1) {
                int kb = (kc + 1) * KC;
                int sn = st ^ 1;
                pa0 = *(const float4*)(xrow + kb + acb * 2);
                pa1 = *(const float4*)(xrow + kb + acb * 2 + 4);
                #pragma unroll
                for (int j = 0; j < 4; j++) {
                    int idx = tid + 256 * j;
                    int row = idx >> 2, seg = (idx & 3) * 8;
                    const __half* src = (row < 128) ? (Wgh + (size_t)row * DIM + kb + seg)
                                                    : (Wuh + (size_t)(row - 128) * DIM + kb + seg);
                    cp16(Bh + sn * BH_HB + row * BH_ST + seg, src);
                }
                cpcommit();
            }
            uint32_t ab = a_base + st * (APL * 4);
            uint32_t bb = bh_base + st * (BH_HB * 2);
            #pragma unroll
            for (int ks = 0; ks < 2; ks++) {
                uint32_t bq[8];
                ldsm4(bq[0], bq[1], bq[2], bq[3], bb + (wid * 16) * 80 + ks * 32);
                ldsm4(bq[4], bq[5], bq[6], bq[7], bb + (128 + wid * 16) * 80 + ks * 32);
                uint32_t ah[4][4];
                #pragma unroll
                for (int rt = 0; rt < 4; rt++)
                    ldsm4(ah[rt][0], ah[rt][1], ah[rt][2], ah[rt][3],
                          ab + rt * 1280 + ks * 32);
                #pragma unroll
                for (int ct = 0; ct < 4; ct++)
                    #pragma unroll
                    for (int rt = 0; rt < 4; rt++)
                        mma16(c[rt][ct], ah[rt], bq[2 * ct], bq[2 * ct + 1]);
            }
        }
    }

    // epilogue: h = silu(gate)*up in regs -> fp16 -> global
    #pragma unroll
    for (int rt = 0; rt < 4; rt++) {
        #pragma unroll
        for (int ct = 0; ct < 2; ct++) {
            int col = ncol0 + wid * 16 + ct * 8 + 2 * l4;
            #pragma unroll
            for (int half = 0; half < 2; half++) {
                int r = rt * 16 + gid + half * 8;
                float g0 = c[rt][ct][half * 2],     u0 = c[rt][ct + 2][half * 2];
                float g1 = c[rt][ct][half * 2 + 1], u1 = c[rt][ct + 2][half * 2 + 1];
                float h0 = (g0 / (1.f + __expf(-g0))) * u0;
                float h1 = (g1 / (1.f + __expf(-g1))) * u1;
                uint32_t hh = h2bits(h0, h1);
                if (is_shared) {
                    size_t gi = (size_t)(m0 + r) * (SINTER / 2) + (col >> 1);
                    g_hs_hi[gi] = hh;
                } else {
                    size_t gi = ((size_t)e * T_TOK + m0 + r) * (INTER / 2) + (col >> 1);
                    g_he_hi[gi] = hh;
                }
            }
        }
    }
}

// ---------------- 4. fused: expert down-projection + final GEMM ----------
// grid (16, NEXP + 2, 2):
//   by < NEXP:  down path  (e=by, n0=bz*256)
//   by >= NEXP: final path (n0=(by-NEXP)*256, k0=bz*512; KSPLIT=2)
__global__ __launch_bounds__(256, 2) void down_final_mma(const float* __restrict__ w2)
{
    extern __shared__ __align__(16) char smc[];
    uint32_t* Au = (uint32_t*)smc;               // [2][64][AK2]
    float*    Bf = (float*)(smc + A_BYTES);      // down: [2][32][BKN_ST] fp32
    __half*   Bh = (__half*)(smc + A_BYTES);     // final: [2][256][BH_ST] fp16

    const int by = blockIdx.y;
    const int bz = blockIdx.z;
    const int tid  = threadIdx.x;
    const int wid  = tid >> 5;
    const int lane = tid & 31;
    const int gid  = lane >> 2;
    const int l4   = lane & 3;
    const int m0   = blockIdx.x * 64;

    const uint32_t a_base = smaddr(Au) + (lane & 15) * 80 + (lane >> 4) * 16;

    float c[4][4][4];
    #pragma unroll
    for (int i = 0; i < 4; i++)
        #pragma unroll
        for (int j = 0; j < 4; j++)
            #pragma unroll
            for (int q = 0; q < 4; q++) c[i][j][q] = 0.f;

    if (by < NEXP) {
        // ================= DOWN PATH (verbatim R15 body) =================
        const int e  = by;
        const int cnt = g_counts[e];
        if (m0 >= cnt) return;
        const int mr = min(64, cnt - m0);
        const int n0 = bz * 256;

        __shared__ int   s_tok[64];
        __shared__ int   s_slot[64];
        __shared__ float s_w[64];
        if (tid < 64) {
            int mm = (tid < mr) ? tid : 0;
            s_tok[tid]  = g_tok[e * T_TOK + m0 + mm];
            s_slot[tid] = g_tslot[e * T_TOK + m0 + mm];
            s_w[tid]    = g_tw[e * T_TOK + m0 + mm];
        }

        const uint32_t* hhi = g_he_hi + ((size_t)e * T_TOK + m0) * (INTER / 2);
        const float* w2base = w2 + (size_t)e * INTER * DIM + n0;
        const int nn[4] = { wid * 32 + gid, wid * 32 + 8 + gid,
                            wid * 32 + 16 + gid, wid * 32 + 24 + gid };

        {
            {
                int row = tid >> 2, seg = (tid & 3) * 4;
                cp16(Au + row * AK2 + seg, hhi + (size_t)row * (INTER / 2) + seg);
            }
            #pragma unroll
            for (int j = 0; j < 8; j++) {
                int idx = tid + 256 * j;
                int kr = idx >> 6, nc = (idx & 63) * 4;
                cp16(&Bf[kr * BKN_ST + nc], w2base + (size_t)kr * DIM + nc);
            }
            cpcommit();
        }
        const int NCH = INTER / KC;   // 8
        for (int kc = 0; kc < NCH; kc++) {
            int st = kc & 1;
            cpwait<0>();
            __syncthreads();
            if (kc < NCH - 1) {
                int kb2 = (kc + 1) * 16;
                int kb  = (kc + 1) * KC;
                int sn = st ^ 1;
                {
                    int row = tid >> 2, seg = (tid & 3) * 4;
                    cp16(Au + sn * APL + row * AK2 + seg,
                         hhi + (size_t)row * (INTER / 2) + kb2 + seg);
                }
                #pragma unroll
                for (int j = 0; j < 8; j++) {
                    int idx = tid + 256 * j;
                    int kr = idx >> 6, nc = (idx & 63) * 4;
                    cp16(&Bf[sn * BKN_FB + kr * BKN_ST + nc],
                         w2base + (size_t)(kb + kr) * DIM + nc);
                }
                cpcommit();
            }
            uint32_t ab = a_base + st * (APL * 4);
            const float* Bsb = Bf + st * BKN_FB;
            #pragma unroll
            for (int ks = 0; ks < 2; ks++) {
                uint32_t bq[8];
                #pragma unroll
                for (int ct = 0; ct < 4; ct++) {
                    int n = nn[ct];
                    int kk = ks * 16 + 2 * l4;
                    bq[2 * ct]     = h2bits(Bsb[kk * BKN_ST + n],       Bsb[(kk + 1) * BKN_ST + n]);
                    bq[2 * ct + 1] = h2bits(Bsb[(kk + 8) * BKN_ST + n], Bsb[(kk + 9) * BKN_ST + n]);
                }
                uint32_t ah[4][4];
                #pragma unroll
                for (int rt = 0; rt < 4; rt++)
                    ldsm4(ah[rt][0], ah[rt][1], ah[rt][2], ah[rt][3],
                          ab + rt * 1280 + ks * 32);
                #pragma unroll
                for (int ct = 0; ct < 4; ct++)
                    #pragma unroll
                    for (int rt = 0; rt < 4; rt++)
                        mma16(c[rt][ct], ah[rt], bq[2 * ct], bq[2 * ct + 1]);
            }
        }

        #pragma unroll
        for (int rt = 0; rt < 4; rt++) {
            #pragma unroll
            for (int ct = 0; ct < 4; ct++) {
                int col = n0 + wid * 32 + ct * 8 + 2 * l4;
                #pragma unroll
                for (int half = 0; half < 2; half++) {
                    int r = rt * 16 + gid + half * 8;
                    if (r < mr) {
                        size_t base = ((size_t)(s_tok[r] * TOPK + s_slot[r])) * DIM + col;
                        float w = s_w[r];
                        *(float2*)&g_contrib[base] =
                            make_float2(w * c[rt][ct][half * 2], w * c[rt][ct][half * 2 + 1]);
                    }
                }
            }
        }
    } else {
        // ================= FINAL PATH (R15 body; K=512 per block) ========
        const int n0 = (by - NEXP) * 256;
        const int k0 = bz * 512;
        const int k02 = k0 / 2;
        const uint32_t b_base = smaddr(Bh) + (((lane >> 4) & 1) * 8 + (lane & 7)) * 80
                                            + ((lane >> 3) & 1) * 16;
        {
            {
                int row = tid >> 2, seg = (tid & 3) * 4;
                cp16(Au + row * AK2 + seg,
                     g_hs_hi + (size_t)(m0 + row) * (SINTER / 2) + k02 + seg);
            }
            #pragma unroll
            for (int j = 0; j < 4; j++) {
                int idx = tid + 256 * j;
                int row = idx >> 2, seg = (idx & 3) * 8;
                cp16(Bh + row * BH_ST + seg,
                     g_wsdh + (size_t)(n0 + row) * SINTER + k0 + seg);
            }
            cpcommit();
        }
        const int NCH = 512 / KC;   // 16
        for (int kc = 0; kc < NCH; kc++) {
            int st = kc & 1;
            cpwait<0>();
            __syncthreads();
            if (kc < NCH - 1) {
                int kb  = (kc + 1) * KC;
                int kb2 = (kc + 1) * 16;
                int sn = st ^ 1;
                {
                    int row = tid >> 2, seg = (tid & 3) * 4;
                    cp16(Au + sn * APL + row * AK2 + seg,
                         g_hs_hi + (size_t)(m0 + row) * (SINTER / 2) + k02 + kb2 + seg);
                }
                #pragma unroll
                for (int j = 0; j < 4; j++) {
                    int idx = tid + 256 * j;
                    int row = idx >> 2, seg = (idx & 3) * 8;
                    cp16(Bh + sn * BH_HB + row * BH_ST + seg,
                         g_wsdh + (size_t)(n0 + row) * SINTER + k0 + kb + seg);
                }
                cpcommit();
            }
            uint32_t ab = a_base + st * (APL * 4);
            uint32_t bb = b_base + st * (BH_HB * 2);
            #pragma unroll
            for (int ks = 0; ks < 2; ks++) {
                uint32_t bq[8];
                ldsm4(bq[0], bq[1], bq[2], bq[3], bb + (wid * 32) * 80 + ks * 32);
                ldsm4(bq[4], bq[5], bq[6], bq[7], bb + (wid * 32 + 16) * 80 + ks * 32);
                uint32_t ah[4][4];
                #pragma unroll
                for (int rt = 0; rt < 4; rt++)
                    ldsm4(ah[rt][0], ah[rt][1], ah[rt][2], ah[rt][3],
                          ab + rt * 1280 + ks * 32);
                #pragma unroll
                for (int ct = 0; ct < 4; ct++)
                    #pragma unroll
                    for (int rt = 0; rt < 4; rt++)
                        mma16(c[rt][ct], ah[rt], bq[2 * ct], bq[2 * ct + 1]);
            }
        }

        #pragma unroll
        for (int rt = 0; rt < 4; rt++) {
            #pragma unroll
            for (int ct = 0; ct < 4; ct++) {
                int col = n0 + wid * 32 + ct * 8 + 2 * l4;
                int r0 = m0 + rt * 16 + gid, r1 = r0 + 8;
                *(float2*)&g_part[((size_t)bz * T_TOK + r0) * DIM + col]
                    = make_float2(c[rt][ct][0], c[rt][ct][1]);
                *(float2*)&g_part[((size_t)bz * T_TOK + r1) * DIM + col]
                    = make_float2(c[rt][ct][2], c[rt][ct][3]);
            }
        }
    }
}

// ---------------- 5. reduce ----------------
__global__ __launch_bounds__(256) void reduce_kernel(float* __restrict__ out)
{
    int t = blockIdx.x;
    #pragma unroll
    for (int h = 0; h < 2; h++) {
        int d = threadIdx.x + h * 256;
        float v = 0.f;
        #pragma unroll
        for (int z = 0; z < KSPLIT; z++)
            v += g_part[((size_t)z * T_TOK + t) * DIM + d];
        #pragma unroll
        for (int k = 0; k < TOPK; k++)
            v += g_contrib[((size_t)t * TOPK + k) * DIM + d];
        out[(size_t)t * DIM + d] = v;
    }
}

// ---------------- launcher ----------------
extern "C" void kernel_launch(void* const* d_in, const int* in_sizes, int n_in,
                              void* d_out, int out_size)
{
    const float* x   = (const float*)d_in[0];
    const float* wg  = (const float*)d_in[1];
    const float* w1  = (const float*)d_in[2];
    const float* w2  = (const float*)d_in[3];
    const float* w3  = (const float*)d_in[4];
    const float* wsg = (const float*)d_in[5];
    const float* wsu = (const float*)d_in[6];
    const float* wsd = (const float*)d_in[7];
    float* out = (float*)d_out;

    const int smem_up = A_BYTES + 2 * BF_FB * 4;     // 10240 + 81920 = 92160
    const int smem_df = A_BYTES + 2 * BKN_FB * 4;    // 10240 + 66560 = 76800 (>= final 51200)

    cudaFuncSetAttribute(up_mma,         cudaFuncAttributeMaxDynamicSharedMemorySize, smem_up);
    cudaFuncSetAttribute(down_final_mma, cudaFuncAttributeMaxDynamicSharedMemorySize, smem_df);

    pre_kernel<<<dim3(256, 4), 256>>>(wsg, wsu, wsd, x, wg);
    group_kernel<<<NEXP, 1024>>>();
    up_mma<<<dim3(16, NEXP * 2 + SINTER / 128), 256, smem_up>>>(x, w1, w3);
    down_final_mma<<<dim3(16, NEXP + 2, 2), 256, smem_df>>>(w2);
    reduce_kernel<<<T_TOK, 256>>>(out);
}